// round 10
// baseline (speedup 1.0000x reference)
#include <cuda_runtime.h>
#include <math.h>

#define D_MODEL 1024
#define SEQ     2048
#define BATCH   2
#define HEADS   16
#define DK      64
#define DFF     4096
#define MROWS   (BATCH * SEQ)   // 4096

// ---------------- scratch (static device allocations) ----------------
__device__ float g_xn  [MROWS * D_MODEL];
__device__ float g_q   [MROWS * D_MODEL];
__device__ float g_k   [MROWS * D_MODEL];
__device__ float g_v   [MROWS * D_MODEL];
__device__ float g_q2  [MROWS * D_MODEL];
__device__ float g_k2  [MROWS * D_MODEL];
__device__ float g_attn[MROWS * D_MODEL];
__device__ float g_a   [(size_t)MROWS * DFF];
__device__ float g_g   [(size_t)MROWS * DFF];

// ---------------- RMSNorm ----------------
__global__ void rmsnorm_kernel(const float* __restrict__ x,
                               const float* __restrict__ w,
                               float* __restrict__ o) {
    int row = blockIdx.x;
    const float* xr = x + (size_t)row * D_MODEL;
    float* orow = o + (size_t)row * D_MODEL;
    int tid = threadIdx.x;

    float s = 0.f;
    #pragma unroll
    for (int i = tid; i < D_MODEL; i += 256) {
        float v = xr[i];
        s += v * v;
    }
    #pragma unroll
    for (int off = 16; off > 0; off >>= 1)
        s += __shfl_xor_sync(0xffffffffu, s, off);
    __shared__ float red[8];
    if ((tid & 31) == 0) red[tid >> 5] = s;
    __syncthreads();
    if (tid < 32) {
        float v = (tid < 8) ? red[tid] : 0.f;
        #pragma unroll
        for (int off = 4; off > 0; off >>= 1)
            v += __shfl_xor_sync(0xffffffffu, v, off);
        if (tid == 0) red[0] = v;
    }
    __syncthreads();
    float inv = rsqrtf(red[0] * (1.0f / D_MODEL) + 1e-5f);
    #pragma unroll
    for (int i = tid; i < D_MODEL; i += 256)
        orow[i] = xr[i] * inv * w[i];
}

// ---------------- SGEMM (NT): C[M,N] = A[M,K] * B[N,K]^T (+ R) ----------------
// NOTE: R and C are deliberately NOT __restrict__ — the final FFN GEMM passes
// R == C == d_out (in-place residual add). Declaring them restrict was UB.
__global__ __launch_bounds__(256) void sgemm_nt_kernel(
    const float* __restrict__ A, const float* __restrict__ B,
    const float* R, float* C,
    int M, int N, int K) {
    __shared__ float As[16][128];
    __shared__ float Bs[16][128];

    int bx = blockIdx.x;
    int by = blockIdx.y;
    int tid = threadIdx.x;

    int ty = tid >> 4;
    int tx = tid & 15;
    int rowb = ty * 8;
    int colb = tx * 8;

    float acc[8][8];
    #pragma unroll
    for (int i = 0; i < 8; i++)
        #pragma unroll
        for (int j = 0; j < 8; j++) acc[i][j] = 0.f;

    for (int k0 = 0; k0 < K; k0 += 16) {
        #pragma unroll
        for (int t = 0; t < 2; t++) {
            int f = tid + t * 256;
            int r = f >> 2;
            int kq = (f & 3) * 4;
            float4 av = *(const float4*)(A + (size_t)(by * 128 + r) * K + k0 + kq);
            float4 bv = *(const float4*)(B + (size_t)(bx * 128 + r) * K + k0 + kq);
            As[kq + 0][r] = av.x; As[kq + 1][r] = av.y;
            As[kq + 2][r] = av.z; As[kq + 3][r] = av.w;
            Bs[kq + 0][r] = bv.x; Bs[kq + 1][r] = bv.y;
            Bs[kq + 2][r] = bv.z; Bs[kq + 3][r] = bv.w;
        }
        __syncthreads();

        #pragma unroll
        for (int k = 0; k < 16; k++) {
            float af[8], bf[8];
            #pragma unroll
            for (int i = 0; i < 8; i++) af[i] = As[k][rowb + i];
            #pragma unroll
            for (int j = 0; j < 8; j++) bf[j] = Bs[k][colb + j];
            #pragma unroll
            for (int i = 0; i < 8; i++)
                #pragma unroll
                for (int j = 0; j < 8; j++)
                    acc[i][j] += af[i] * bf[j];
        }
        __syncthreads();
    }

    #pragma unroll
    for (int i = 0; i < 8; i++) {
        size_t crow = (size_t)(by * 128 + rowb + i) * N + bx * 128 + colb;
        if (R) {
            #pragma unroll
            for (int j = 0; j < 8; j++) acc[i][j] += R[crow + j];
        }
        #pragma unroll
        for (int j = 0; j < 8; j++)
            C[crow + j] = acc[i][j];
    }
}

// ---------------- RoPE (double precision, NOT in place) ----------------
// one thread per (bs, head, pair). Reads raw q/k, writes rotated copies.
__global__ void rope_dbl_kernel(const float* __restrict__ qin,
                                const float* __restrict__ kin,
                                float* __restrict__ qout,
                                float* __restrict__ kout,
                                const int* __restrict__ pos) {
    int bs = blockIdx.x;
    int h  = threadIdx.x >> 5;
    int i  = threadIdx.x & 31;
    int p  = pos[bs];

    double freq = exp(-((double)(2 * i) / 64.0) * log(10000.0));
    double ang = (double)p * freq;
    double cd, sd;
    sincos(ang, &sd, &cd);
    float c = (float)cd, s = (float)sd;

    size_t base = (size_t)bs * D_MODEL + h * DK + 2 * i;
    float qe = qin[base], qo = qin[base + 1];
    qout[base]     = qe * c - qo * s;
    qout[base + 1] = qe * s + qo * c;
    float ke = kin[base], ko = kin[base + 1];
    kout[base]     = ke * c - ko * s;
    kout[base + 1] = ke * s + ko * c;
}

// ---------------- NAIVE causal attention (diagnosis build) ----------------
// One thread per query row per (b,h). No smem, no float4, no restrict on data.
// Two-pass softmax, everything read scalar from global memory.
__global__ __launch_bounds__(128) void attn_naive_kernel(
    const float* Q, const float* K, const float* V, float* O) {
    int qi = blockIdx.x * 128 + threadIdx.x;
    int h  = blockIdx.y;
    int b  = blockIdx.z;

    const float* qp = Q + ((size_t)(b * SEQ + qi)) * D_MODEL + h * DK;
    float qreg[64];
    for (int d = 0; d < 64; d++) qreg[d] = qp[d];

    const float scale = 0.125f;

    // pass 1: max
    float m = -INFINITY;
    for (int j = 0; j <= qi; j++) {
        const float* kp = K + ((size_t)(b * SEQ + j)) * D_MODEL + h * DK;
        float s = 0.f;
        for (int d = 0; d < 64; d++) s += qreg[d] * kp[d];
        s *= scale;
        if (s > m) m = s;
    }

    // pass 2: exp-sum + V accumulate
    float l = 0.f;
    float acc[64];
    for (int d = 0; d < 64; d++) acc[d] = 0.f;
    for (int j = 0; j <= qi; j++) {
        const float* kp = K + ((size_t)(b * SEQ + j)) * D_MODEL + h * DK;
        float s = 0.f;
        for (int d = 0; d < 64; d++) s += qreg[d] * kp[d];
        float p = __expf(s * scale - m);
        l += p;
        const float* vp = V + ((size_t)(b * SEQ + j)) * D_MODEL + h * DK;
        for (int d = 0; d < 64; d++) acc[d] += p * vp[d];
    }

    float inv = 1.f / l;
    float* op = O + ((size_t)(b * SEQ + qi)) * D_MODEL + h * DK;
    for (int d = 0; d < 64; d++) op[d] = acc[d] * inv;
}

// ---------------- h = silu(a) * g ----------------
__global__ void silumul_kernel(float* a, const float* g, int n) {
    int i = blockIdx.x * blockDim.x + threadIdx.x;
    if (i >= n) return;
    float av = a[i], gv = g[i];
    a[i] = av / (1.f + __expf(-av)) * gv;
}

// ---------------- launch ----------------
extern "C" void kernel_launch(void* const* d_in, const int* in_sizes, int n_in,
                              void* d_out, int out_size) {
    const float* x    = (const float*)d_in[0];
    const int*   pos  = (const int*)  d_in[1];
    const float* n1w  = (const float*)d_in[2];
    const float* n2w  = (const float*)d_in[3];
    const float* wq   = (const float*)d_in[4];
    const float* wk   = (const float*)d_in[5];
    const float* wv   = (const float*)d_in[6];
    const float* wo   = (const float*)d_in[7];
    const float* w1   = (const float*)d_in[8];
    const float* w2   = (const float*)d_in[9];
    const float* w3   = (const float*)d_in[10];
    float* out = (float*)d_out;

    float *xn, *q, *k, *v, *q2, *k2, *attn, *a, *g;
    cudaGetSymbolAddress((void**)&xn,   g_xn);
    cudaGetSymbolAddress((void**)&q,    g_q);
    cudaGetSymbolAddress((void**)&k,    g_k);
    cudaGetSymbolAddress((void**)&v,    g_v);
    cudaGetSymbolAddress((void**)&q2,   g_q2);
    cudaGetSymbolAddress((void**)&k2,   g_k2);
    cudaGetSymbolAddress((void**)&attn, g_attn);
    cudaGetSymbolAddress((void**)&a,    g_a);
    cudaGetSymbolAddress((void**)&g,    g_g);

    // 1) xn = rmsnorm(x, norm1_w)
    rmsnorm_kernel<<<MROWS, 256>>>(x, n1w, xn);

    // 2) q/k/v projections
    dim3 gD(D_MODEL / 128, MROWS / 128);
    sgemm_nt_kernel<<<gD, 256>>>(xn, wq, nullptr, q, MROWS, D_MODEL, D_MODEL);
    sgemm_nt_kernel<<<gD, 256>>>(xn, wk, nullptr, k, MROWS, D_MODEL, D_MODEL);
    sgemm_nt_kernel<<<gD, 256>>>(xn, wv, nullptr, v, MROWS, D_MODEL, D_MODEL);

    // 3) RoPE (double precision, out-of-place)
    rope_dbl_kernel<<<MROWS, 512>>>(q, k, q2, k2, pos);

    // 4) naive causal attention
    attn_naive_kernel<<<dim3(SEQ / 128, HEADS, BATCH), 128>>>(q2, k2, v, attn);

    // 5) out = x + attn @ wo^T
    sgemm_nt_kernel<<<gD, 256>>>(attn, wo, x, out, MROWS, D_MODEL, D_MODEL);

    // 6) xn = rmsnorm(out, norm2_w)
    rmsnorm_kernel<<<MROWS, 256>>>(out, n2w, xn);

    // 7) a = xn @ w1^T ; g = xn @ w3^T
    dim3 gF(DFF / 128, MROWS / 128);
    sgemm_nt_kernel<<<gF, 256>>>(xn, w1, nullptr, a, MROWS, DFF, D_MODEL);
    sgemm_nt_kernel<<<gF, 256>>>(xn, w3, nullptr, g, MROWS, DFF, D_MODEL);

    // 8) a = silu(a) * g
    int n = MROWS * DFF;
    silumul_kernel<<<(n + 255) / 256, 256>>>(a, g, n);

    // 9) out = out + a @ w2^T   (R == C: aliasing now legal)
    sgemm_nt_kernel<<<gD, 256>>>(a, w2, out, out, MROWS, D_MODEL, DFF);
}

// round 11
// speedup vs baseline: 3.0095x; 3.0095x over previous
#include <cuda_runtime.h>
#include <math.h>
#include <stdint.h>

#define D_MODEL 1024
#define SEQ     2048
#define BATCH   2
#define HEADS   16
#define DK      64
#define DFF     4096
#define MROWS   (BATCH * SEQ)   // 4096

// ---------------- scratch (static device allocations) ----------------
__device__ float g_xn  [MROWS * D_MODEL];
__device__ float g_q   [MROWS * D_MODEL];
__device__ float g_k   [MROWS * D_MODEL];
__device__ float g_v   [MROWS * D_MODEL];
__device__ float g_q2  [MROWS * D_MODEL];
__device__ float g_k2  [MROWS * D_MODEL];
__device__ float g_attn[MROWS * D_MODEL];
__device__ float g_a   [(size_t)MROWS * DFF];
__device__ float g_g   [(size_t)MROWS * DFF];

// ---------------- RMSNorm ----------------
__global__ void rmsnorm_kernel(const float* __restrict__ x,
                               const float* __restrict__ w,
                               float* __restrict__ o) {
    int row = blockIdx.x;
    const float* xr = x + (size_t)row * D_MODEL;
    float* orow = o + (size_t)row * D_MODEL;
    int tid = threadIdx.x;

    float s = 0.f;
    #pragma unroll
    for (int i = tid; i < D_MODEL; i += 256) {
        float v = xr[i];
        s += v * v;
    }
    #pragma unroll
    for (int off = 16; off > 0; off >>= 1)
        s += __shfl_xor_sync(0xffffffffu, s, off);
    __shared__ float red[8];
    if ((tid & 31) == 0) red[tid >> 5] = s;
    __syncthreads();
    if (tid < 32) {
        float v = (tid < 8) ? red[tid] : 0.f;
        #pragma unroll
        for (int off = 4; off > 0; off >>= 1)
            v += __shfl_xor_sync(0xffffffffu, v, off);
        if (tid == 0) red[0] = v;
    }
    __syncthreads();
    float inv = rsqrtf(red[0] * (1.0f / D_MODEL) + 1e-5f);
    #pragma unroll
    for (int i = tid; i < D_MODEL; i += 256)
        orow[i] = xr[i] * inv * w[i];
}

// ---------------- TF32 tensor-core GEMM (NT): C = A[M,K]*B[N,K]^T (+R) ----------------
// BM=BN=128, BK=16, 256 threads = 8 warps in 2(m)x4(n) grid, warp tile 64x32.
// mma.sync.m16n8k8 tf32. Smem rows padded to stride 20 floats -> fragment
// reads are conflict-free (20*grp+qid covers all 32 banks over grp=0..7).
// R/C deliberately NOT __restrict__ (final FFN GEMM passes R==C==d_out).
__device__ __forceinline__ uint32_t f2tf32(float f) {
    uint32_t u;
    asm("cvt.rna.tf32.f32 %0, %1;" : "=r"(u) : "f"(f));
    return u;
}

__global__ __launch_bounds__(256) void mma_tf32_nt_kernel(
    const float* __restrict__ A, const float* __restrict__ B,
    const float* R, float* C, int M, int N, int K) {
    __shared__ float As[128 * 20];
    __shared__ float Bs[128 * 20];

    int tid  = threadIdx.x;
    int wid  = tid >> 5;
    int lane = tid & 31;
    int grp  = lane >> 2;   // 0..7
    int qid  = lane & 3;    // 0..3

    int wm = (wid & 1) * 64;    // warp m offset
    int wn = (wid >> 1) * 32;   // warp n offset

    int bx = blockIdx.x;   // N tile
    int by = blockIdx.y;   // M tile

    float c[4][4][4];
    #pragma unroll
    for (int mt = 0; mt < 4; mt++)
        #pragma unroll
        for (int nt = 0; nt < 4; nt++)
            #pragma unroll
            for (int i = 0; i < 4; i++) c[mt][nt][i] = 0.f;

    for (int k0 = 0; k0 < K; k0 += 16) {
        // stage 128x16 A and B tiles (256 threads x 2 float4 per matrix)
        #pragma unroll
        for (int t = 0; t < 2; t++) {
            int f = tid + t * 256;       // 0..511
            int r = f >> 2;
            int kq = (f & 3) * 4;
            float4 av = *(const float4*)(A + (size_t)(by * 128 + r) * K + k0 + kq);
            float4 bv = *(const float4*)(B + (size_t)(bx * 128 + r) * K + k0 + kq);
            *(float4*)(&As[r * 20 + kq]) = av;
            *(float4*)(&Bs[r * 20 + kq]) = bv;
        }
        __syncthreads();

        #pragma unroll
        for (int kk = 0; kk < 16; kk += 8) {
            uint32_t af[4][4], bf[4][2];
            #pragma unroll
            for (int mt = 0; mt < 4; mt++) {
                int r0 = wm + mt * 16 + grp;
                af[mt][0] = f2tf32(As[r0 * 20 + kk + qid]);
                af[mt][1] = f2tf32(As[(r0 + 8) * 20 + kk + qid]);
                af[mt][2] = f2tf32(As[r0 * 20 + kk + qid + 4]);
                af[mt][3] = f2tf32(As[(r0 + 8) * 20 + kk + qid + 4]);
            }
            #pragma unroll
            for (int nt = 0; nt < 4; nt++) {
                int n0 = wn + nt * 8 + grp;
                bf[nt][0] = f2tf32(Bs[n0 * 20 + kk + qid]);
                bf[nt][1] = f2tf32(Bs[n0 * 20 + kk + qid + 4]);
            }
            #pragma unroll
            for (int mt = 0; mt < 4; mt++)
                #pragma unroll
                for (int nt = 0; nt < 4; nt++)
                    asm volatile(
                        "mma.sync.aligned.m16n8k8.row.col.f32.tf32.tf32.f32 "
                        "{%0,%1,%2,%3}, {%4,%5,%6,%7}, {%8,%9}, {%0,%1,%2,%3};"
                        : "+f"(c[mt][nt][0]), "+f"(c[mt][nt][1]),
                          "+f"(c[mt][nt][2]), "+f"(c[mt][nt][3])
                        : "r"(af[mt][0]), "r"(af[mt][1]),
                          "r"(af[mt][2]), "r"(af[mt][3]),
                          "r"(bf[nt][0]), "r"(bf[nt][1]));
        }
        __syncthreads();
    }

    // epilogue: c0,c1 -> (row, col..col+1), c2,c3 -> (row+8, col..col+1)
    #pragma unroll
    for (int mt = 0; mt < 4; mt++) {
        int row = by * 128 + wm + mt * 16 + grp;
        #pragma unroll
        for (int nt = 0; nt < 4; nt++) {
            int col = bx * 128 + wn + nt * 8 + qid * 2;
            size_t i0 = (size_t)row * N + col;
            size_t i1 = (size_t)(row + 8) * N + col;
            float v00 = c[mt][nt][0], v01 = c[mt][nt][1];
            float v10 = c[mt][nt][2], v11 = c[mt][nt][3];
            if (R) {
                v00 += R[i0]; v01 += R[i0 + 1];
                v10 += R[i1]; v11 += R[i1 + 1];
            }
            *(float2*)(C + i0) = make_float2(v00, v01);
            *(float2*)(C + i1) = make_float2(v10, v11);
        }
    }
}

// ---------------- RoPE (double precision, out-of-place; validated) ----------------
__global__ void rope_dbl_kernel(const float* __restrict__ qin,
                                const float* __restrict__ kin,
                                float* __restrict__ qout,
                                float* __restrict__ kout,
                                const int* __restrict__ pos) {
    int bs = blockIdx.x;
    int h  = threadIdx.x >> 5;
    int i  = threadIdx.x & 31;
    int p  = pos[bs];

    double freq = exp(-((double)(2 * i) / 64.0) * log(10000.0));
    double ang = (double)p * freq;
    double cd, sd;
    sincos(ang, &sd, &cd);
    float c = (float)cd, s = (float)sd;

    size_t base = (size_t)bs * D_MODEL + h * DK + 2 * i;
    float qe = qin[base], qo = qin[base + 1];
    qout[base]     = qe * c - qo * s;
    qout[base + 1] = qe * s + qo * c;
    float ke = kin[base], ko = kin[base + 1];
    kout[base]     = ke * c - ko * s;
    kout[base + 1] = ke * s + ko * c;
}

// ---------------- Causal flash attention (single-pass online softmax) ----------------
// grid (SEQ/128, H, B), block 128 = one thread per query row.
// 64x64 K/V tiles in smem; per step all threads read the SAME smem row
// (broadcast, conflict-free) -> FFMA-bound, ~17 GFLOP total.
__global__ __launch_bounds__(128) void attn_flash_kernel(
    const float* __restrict__ Q, const float* __restrict__ K,
    const float* __restrict__ V, float* __restrict__ O) {
    __shared__ __align__(16) float Ks[64][64];
    __shared__ __align__(16) float Vs[64][64];

    int q0 = blockIdx.x * 128;
    int h  = blockIdx.y;
    int b  = blockIdx.z;
    int t  = threadIdx.x;
    int qi = q0 + t;

    size_t headoff = (size_t)b * SEQ * D_MODEL + h * DK;

    float qf[64];
    const float* qrow = Q + headoff + (size_t)qi * D_MODEL;
    #pragma unroll
    for (int d = 0; d < 64; d += 4) {
        float4 v4 = *(const float4*)(qrow + d);
        qf[d] = v4.x; qf[d+1] = v4.y; qf[d+2] = v4.z; qf[d+3] = v4.w;
    }

    const float scale = 0.125f;
    int nkv = q0 + 128;

    float m = -INFINITY, l = 0.f;
    float acc[64];
    #pragma unroll
    for (int d = 0; d < 64; d++) acc[d] = 0.f;

    for (int kv = 0; kv < nkv; kv += 64) {
        __syncthreads();
        for (int idx = t; idx < 64 * 16; idx += 128) {
            int r = idx >> 4, c = (idx & 15) * 4;
            *(float4*)&Ks[r][c] =
                *(const float4*)(K + headoff + (size_t)(kv + r) * D_MODEL + c);
            *(float4*)&Vs[r][c] =
                *(const float4*)(V + headoff + (size_t)(kv + r) * D_MODEL + c);
        }
        __syncthreads();

        int jmax = qi - kv + 1;
        if (jmax > 64) jmax = 64;
        for (int jj = 0; jj < jmax; jj++) {
            float s = 0.f;
            #pragma unroll
            for (int d4 = 0; d4 < 16; d4++) {
                float4 kk = *(const float4*)&Ks[jj][d4 * 4];
                s += qf[4*d4+0]*kk.x + qf[4*d4+1]*kk.y
                   + qf[4*d4+2]*kk.z + qf[4*d4+3]*kk.w;
            }
            s *= scale;
            if (s > m) {
                float corr = __expf(m - s);   // exp(-inf)=0 on first step
                l *= corr;
                #pragma unroll
                for (int d = 0; d < 64; d++) acc[d] *= corr;
                m = s;
            }
            float p = __expf(s - m);
            l += p;
            #pragma unroll
            for (int d4 = 0; d4 < 16; d4++) {
                float4 vv = *(const float4*)&Vs[jj][d4 * 4];
                acc[4*d4+0] += p * vv.x; acc[4*d4+1] += p * vv.y;
                acc[4*d4+2] += p * vv.z; acc[4*d4+3] += p * vv.w;
            }
        }
    }

    float inv = 1.f / l;
    float* orow = O + headoff + (size_t)qi * D_MODEL;
    #pragma unroll
    for (int d = 0; d < 64; d += 4) {
        float4 v4 = make_float4(acc[d] * inv, acc[d+1] * inv,
                                acc[d+2] * inv, acc[d+3] * inv);
        *(float4*)(orow + d) = v4;
    }
}

// ---------------- h = silu(a) * g ----------------
__global__ void silumul_kernel(float* a, const float* g, int n) {
    int i = blockIdx.x * blockDim.x + threadIdx.x;
    if (i >= n) return;
    float av = a[i], gv = g[i];
    a[i] = av / (1.f + __expf(-av)) * gv;
}

// ---------------- launch ----------------
extern "C" void kernel_launch(void* const* d_in, const int* in_sizes, int n_in,
                              void* d_out, int out_size) {
    const float* x    = (const float*)d_in[0];
    const int*   pos  = (const int*)  d_in[1];
    const float* n1w  = (const float*)d_in[2];
    const float* n2w  = (const float*)d_in[3];
    const float* wq   = (const float*)d_in[4];
    const float* wk   = (const float*)d_in[5];
    const float* wv   = (const float*)d_in[6];
    const float* wo   = (const float*)d_in[7];
    const float* w1   = (const float*)d_in[8];
    const float* w2   = (const float*)d_in[9];
    const float* w3   = (const float*)d_in[10];
    float* out = (float*)d_out;

    float *xn, *q, *k, *v, *q2, *k2, *attn, *a, *g;
    cudaGetSymbolAddress((void**)&xn,   g_xn);
    cudaGetSymbolAddress((void**)&q,    g_q);
    cudaGetSymbolAddress((void**)&k,    g_k);
    cudaGetSymbolAddress((void**)&v,    g_v);
    cudaGetSymbolAddress((void**)&q2,   g_q2);
    cudaGetSymbolAddress((void**)&k2,   g_k2);
    cudaGetSymbolAddress((void**)&attn, g_attn);
    cudaGetSymbolAddress((void**)&a,    g_a);
    cudaGetSymbolAddress((void**)&g,    g_g);

    // 1) xn = rmsnorm(x, norm1_w)
    rmsnorm_kernel<<<MROWS, 256>>>(x, n1w, xn);

    // 2) q/k/v projections (tf32 tensor cores)
    dim3 gD(D_MODEL / 128, MROWS / 128);
    mma_tf32_nt_kernel<<<gD, 256>>>(xn, wq, nullptr, q, MROWS, D_MODEL, D_MODEL);
    mma_tf32_nt_kernel<<<gD, 256>>>(xn, wk, nullptr, k, MROWS, D_MODEL, D_MODEL);
    mma_tf32_nt_kernel<<<gD, 256>>>(xn, wv, nullptr, v, MROWS, D_MODEL, D_MODEL);

    // 3) RoPE (out-of-place, fp64 angles)
    rope_dbl_kernel<<<MROWS, 512>>>(q, k, q2, k2, pos);

    // 4) causal flash attention (online softmax)
    attn_flash_kernel<<<dim3(SEQ / 128, HEADS, BATCH), 128>>>(q2, k2, v, attn);

    // 5) out = x + attn @ wo^T
    mma_tf32_nt_kernel<<<gD, 256>>>(attn, wo, x, out, MROWS, D_MODEL, D_MODEL);

    // 6) xn = rmsnorm(out, norm2_w)
    rmsnorm_kernel<<<MROWS, 256>>>(out, n2w, xn);

    // 7) a = xn @ w1^T ; g = xn @ w3^T
    dim3 gF(DFF / 128, MROWS / 128);
    mma_tf32_nt_kernel<<<gF, 256>>>(xn, w1, nullptr, a, MROWS, DFF, D_MODEL);
    mma_tf32_nt_kernel<<<gF, 256>>>(xn, w3, nullptr, g, MROWS, DFF, D_MODEL);

    // 8) a = silu(a) * g
    int n = MROWS * DFF;
    silumul_kernel<<<(n + 255) / 256, 256>>>(a, g, n);

    // 9) out = out + a @ w2^T   (R == C aliasing is legal: no restrict)
    mma_tf32_nt_kernel<<<gD, 256>>>(a, w2, out, out, MROWS, D_MODEL, DFF);
}

// round 12
// speedup vs baseline: 4.0760x; 1.3544x over previous
#include <cuda_runtime.h>
#include <math.h>
#include <stdint.h>

#define D_MODEL 1024
#define SEQ     2048
#define BATCH   2
#define HEADS   16
#define DK      64
#define DFF     4096
#define MROWS   (BATCH * SEQ)   // 4096

// ---------------- scratch (static device allocations) ----------------
__device__ float g_xn  [MROWS * D_MODEL];
__device__ float g_q   [MROWS * D_MODEL];
__device__ float g_k   [MROWS * D_MODEL];
__device__ float g_v   [MROWS * D_MODEL];
__device__ float g_q2  [MROWS * D_MODEL];
__device__ float g_k2  [MROWS * D_MODEL];
__device__ float g_attn[MROWS * D_MODEL];
__device__ float g_a   [(size_t)MROWS * DFF];
__device__ float g_g   [(size_t)MROWS * DFF];

__device__ __forceinline__ uint32_t f2tf32(float f) {
    uint32_t u;
    asm("cvt.rna.tf32.f32 %0, %1;" : "=r"(u) : "f"(f));
    return u;
}

#define MMA_TF32(c0,c1,c2,c3,a0,a1,a2,a3,b0,b1)                         \
    asm volatile(                                                        \
        "mma.sync.aligned.m16n8k8.row.col.f32.tf32.tf32.f32 "           \
        "{%0,%1,%2,%3}, {%4,%5,%6,%7}, {%8,%9}, {%0,%1,%2,%3};"         \
        : "+f"(c0), "+f"(c1), "+f"(c2), "+f"(c3)                         \
        : "r"(a0), "r"(a1), "r"(a2), "r"(a3), "r"(b0), "r"(b1))

// ---------------- RMSNorm ----------------
__global__ void rmsnorm_kernel(const float* __restrict__ x,
                               const float* __restrict__ w,
                               float* __restrict__ o) {
    int row = blockIdx.x;
    const float* xr = x + (size_t)row * D_MODEL;
    float* orow = o + (size_t)row * D_MODEL;
    int tid = threadIdx.x;

    float s = 0.f;
    #pragma unroll
    for (int i = tid; i < D_MODEL; i += 256) {
        float v = xr[i];
        s += v * v;
    }
    #pragma unroll
    for (int off = 16; off > 0; off >>= 1)
        s += __shfl_xor_sync(0xffffffffu, s, off);
    __shared__ float red[8];
    if ((tid & 31) == 0) red[tid >> 5] = s;
    __syncthreads();
    if (tid < 32) {
        float v = (tid < 8) ? red[tid] : 0.f;
        #pragma unroll
        for (int off = 4; off > 0; off >>= 1)
            v += __shfl_xor_sync(0xffffffffu, v, off);
        if (tid == 0) red[0] = v;
    }
    __syncthreads();
    float inv = rsqrtf(red[0] * (1.0f / D_MODEL) + 1e-5f);
    #pragma unroll
    for (int i = tid; i < D_MODEL; i += 256)
        orow[i] = xr[i] * inv * w[i];
}

// ---------------- TF32 tensor-core GEMM (NT): C = A[M,K]*B[N,K]^T (+R) ----------------
// R/C deliberately NOT __restrict__ (final FFN GEMM passes R==C==d_out).
__global__ __launch_bounds__(256) void mma_tf32_nt_kernel(
    const float* __restrict__ A, const float* __restrict__ B,
    const float* R, float* C, int M, int N, int K) {
    __shared__ float As[128 * 20];
    __shared__ float Bs[128 * 20];

    int tid  = threadIdx.x;
    int wid  = tid >> 5;
    int lane = tid & 31;
    int grp  = lane >> 2;
    int qid  = lane & 3;

    int wm = (wid & 1) * 64;
    int wn = (wid >> 1) * 32;

    int bx = blockIdx.x;
    int by = blockIdx.y;

    float c[4][4][4];
    #pragma unroll
    for (int mt = 0; mt < 4; mt++)
        #pragma unroll
        for (int nt = 0; nt < 4; nt++)
            #pragma unroll
            for (int i = 0; i < 4; i++) c[mt][nt][i] = 0.f;

    for (int k0 = 0; k0 < K; k0 += 16) {
        #pragma unroll
        for (int t = 0; t < 2; t++) {
            int f = tid + t * 256;
            int r = f >> 2;
            int kq = (f & 3) * 4;
            float4 av = *(const float4*)(A + (size_t)(by * 128 + r) * K + k0 + kq);
            float4 bv = *(const float4*)(B + (size_t)(bx * 128 + r) * K + k0 + kq);
            *(float4*)(&As[r * 20 + kq]) = av;
            *(float4*)(&Bs[r * 20 + kq]) = bv;
        }
        __syncthreads();

        #pragma unroll
        for (int kk = 0; kk < 16; kk += 8) {
            uint32_t af[4][4], bf[4][2];
            #pragma unroll
            for (int mt = 0; mt < 4; mt++) {
                int r0 = wm + mt * 16 + grp;
                af[mt][0] = f2tf32(As[r0 * 20 + kk + qid]);
                af[mt][1] = f2tf32(As[(r0 + 8) * 20 + kk + qid]);
                af[mt][2] = f2tf32(As[r0 * 20 + kk + qid + 4]);
                af[mt][3] = f2tf32(As[(r0 + 8) * 20 + kk + qid + 4]);
            }
            #pragma unroll
            for (int nt = 0; nt < 4; nt++) {
                int n0 = wn + nt * 8 + grp;
                bf[nt][0] = f2tf32(Bs[n0 * 20 + kk + qid]);
                bf[nt][1] = f2tf32(Bs[n0 * 20 + kk + qid + 4]);
            }
            #pragma unroll
            for (int mt = 0; mt < 4; mt++)
                #pragma unroll
                for (int nt = 0; nt < 4; nt++)
                    MMA_TF32(c[mt][nt][0], c[mt][nt][1], c[mt][nt][2], c[mt][nt][3],
                             af[mt][0], af[mt][1], af[mt][2], af[mt][3],
                             bf[nt][0], bf[nt][1]);
        }
        __syncthreads();
    }

    #pragma unroll
    for (int mt = 0; mt < 4; mt++) {
        int row = by * 128 + wm + mt * 16 + grp;
        #pragma unroll
        for (int nt = 0; nt < 4; nt++) {
            int col = bx * 128 + wn + nt * 8 + qid * 2;
            size_t i0 = (size_t)row * N + col;
            size_t i1 = (size_t)(row + 8) * N + col;
            float v00 = c[mt][nt][0], v01 = c[mt][nt][1];
            float v10 = c[mt][nt][2], v11 = c[mt][nt][3];
            if (R) {
                v00 += R[i0]; v01 += R[i0 + 1];
                v10 += R[i1]; v11 += R[i1 + 1];
            }
            *(float2*)(C + i0) = make_float2(v00, v01);
            *(float2*)(C + i1) = make_float2(v10, v11);
        }
    }
}

// ---------------- RoPE (double precision, out-of-place; validated) ----------------
__global__ void rope_dbl_kernel(const float* __restrict__ qin,
                                const float* __restrict__ kin,
                                float* __restrict__ qout,
                                float* __restrict__ kout,
                                const int* __restrict__ pos) {
    int bs = blockIdx.x;
    int h  = threadIdx.x >> 5;
    int i  = threadIdx.x & 31;
    int p  = pos[bs];

    double freq = exp(-((double)(2 * i) / 64.0) * log(10000.0));
    double ang = (double)p * freq;
    double cd, sd;
    sincos(ang, &sd, &cd);
    float c = (float)cd, s = (float)sd;

    size_t base = (size_t)bs * D_MODEL + h * DK + 2 * i;
    float qe = qin[base], qo = qin[base + 1];
    qout[base]     = qe * c - qo * s;
    qout[base + 1] = qe * s + qo * c;
    float ke = kin[base], ko = kin[base + 1];
    kout[base]     = ke * c - ko * s;
    kout[base + 1] = ke * s + ko * c;
}

// ---------------- Tensor-core causal flash attention (tf32 mma) ----------------
// grid (SEQ/128, H, B), block 256 = 8 warps x 16 q-rows.
// Q as A-fragments in registers; K/V 64x68 tiles in smem; online softmax on
// S fragments; P C-layout -> A-layout via quad shuffles.
__global__ __launch_bounds__(256) void attn_mma_kernel(
    const float* __restrict__ Q, const float* __restrict__ K,
    const float* __restrict__ V, float* __restrict__ O) {
    __shared__ float Ks[64][68];
    __shared__ float Vs[64][68];

    int tid  = threadIdx.x;
    int wid  = tid >> 5;
    int lane = tid & 31;
    int grp  = lane >> 2;   // 0..7
    int qid  = lane & 3;    // 0..3

    int q0 = blockIdx.x * 128;
    int h  = blockIdx.y;
    int b  = blockIdx.z;

    int r0 = q0 + wid * 16 + grp;     // this thread's two q rows
    int r1 = r0 + 8;
    size_t headoff = (size_t)b * SEQ * D_MODEL + h * DK;

    // Q A-fragments: qa[ks] covers dims 8ks..8ks+7
    uint32_t qa[8][4];
    {
        const float* q0p = Q + headoff + (size_t)r0 * D_MODEL;
        const float* q1p = Q + headoff + (size_t)r1 * D_MODEL;
        #pragma unroll
        for (int ks = 0; ks < 8; ks++) {
            qa[ks][0] = f2tf32(q0p[8 * ks + qid]);
            qa[ks][1] = f2tf32(q1p[8 * ks + qid]);
            qa[ks][2] = f2tf32(q0p[8 * ks + qid + 4]);
            qa[ks][3] = f2tf32(q1p[8 * ks + qid + 4]);
        }
    }

    float oc[8][4];
    #pragma unroll
    for (int nn = 0; nn < 8; nn++)
        #pragma unroll
        for (int i = 0; i < 4; i++) oc[nn][i] = 0.f;
    float m0 = -INFINITY, m1 = -INFINITY, l0 = 0.f, l1 = 0.f;
    const float scale = 0.125f;

    for (int kv = 0; kv < q0 + 128; kv += 64) {
        __syncthreads();
        for (int idx = tid; idx < 64 * 16; idx += 256) {
            int r = idx >> 4, c = (idx & 15) * 4;
            const float* kp = K + headoff + (size_t)(kv + r) * D_MODEL + c;
            const float* vp = V + headoff + (size_t)(kv + r) * D_MODEL + c;
            *(float4*)&Ks[r][c] = *(const float4*)kp;
            *(float4*)&Vs[r][c] = *(const float4*)vp;
        }
        __syncthreads();

        // ---- S = Q K^T (scores), 128x64 per block, 16x64 per warp ----
        float sc[8][4];
        #pragma unroll
        for (int nn = 0; nn < 8; nn++) {
            sc[nn][0] = sc[nn][1] = sc[nn][2] = sc[nn][3] = 0.f;
            #pragma unroll
            for (int ks = 0; ks < 8; ks++) {
                uint32_t b0 = f2tf32(Ks[8 * nn + grp][8 * ks + qid]);
                uint32_t b1 = f2tf32(Ks[8 * nn + grp][8 * ks + qid + 4]);
                MMA_TF32(sc[nn][0], sc[nn][1], sc[nn][2], sc[nn][3],
                         qa[ks][0], qa[ks][1], qa[ks][2], qa[ks][3], b0, b1);
            }
        }

        // ---- scale + causal mask ----
        #pragma unroll
        for (int nn = 0; nn < 8; nn++) {
            int col = kv + 8 * nn + 2 * qid;
            sc[nn][0] = (col     <= r0) ? sc[nn][0] * scale : -INFINITY;
            sc[nn][1] = (col + 1 <= r0) ? sc[nn][1] * scale : -INFINITY;
            sc[nn][2] = (col     <= r1) ? sc[nn][2] * scale : -INFINITY;
            sc[nn][3] = (col + 1 <= r1) ? sc[nn][3] * scale : -INFINITY;
        }

        // ---- online softmax ----
        float tm0 = -INFINITY, tm1 = -INFINITY;
        #pragma unroll
        for (int nn = 0; nn < 8; nn++) {
            tm0 = fmaxf(tm0, fmaxf(sc[nn][0], sc[nn][1]));
            tm1 = fmaxf(tm1, fmaxf(sc[nn][2], sc[nn][3]));
        }
        tm0 = fmaxf(tm0, __shfl_xor_sync(0xffffffffu, tm0, 1));
        tm0 = fmaxf(tm0, __shfl_xor_sync(0xffffffffu, tm0, 2));
        tm1 = fmaxf(tm1, __shfl_xor_sync(0xffffffffu, tm1, 1));
        tm1 = fmaxf(tm1, __shfl_xor_sync(0xffffffffu, tm1, 2));

        float nm0 = fmaxf(m0, tm0), nm1 = fmaxf(m1, tm1);
        float corr0 = __expf(m0 - nm0), corr1 = __expf(m1 - nm1);
        m0 = nm0; m1 = nm1;

        float sum0 = 0.f, sum1 = 0.f;
        #pragma unroll
        for (int nn = 0; nn < 8; nn++) {
            sc[nn][0] = __expf(sc[nn][0] - nm0);
            sc[nn][1] = __expf(sc[nn][1] - nm0);
            sc[nn][2] = __expf(sc[nn][2] - nm1);
            sc[nn][3] = __expf(sc[nn][3] - nm1);
            sum0 += sc[nn][0] + sc[nn][1];
            sum1 += sc[nn][2] + sc[nn][3];
        }
        sum0 += __shfl_xor_sync(0xffffffffu, sum0, 1);
        sum0 += __shfl_xor_sync(0xffffffffu, sum0, 2);
        sum1 += __shfl_xor_sync(0xffffffffu, sum1, 1);
        sum1 += __shfl_xor_sync(0xffffffffu, sum1, 2);
        l0 = l0 * corr0 + sum0;
        l1 = l1 * corr1 + sum1;

        #pragma unroll
        for (int nn = 0; nn < 8; nn++) {
            oc[nn][0] *= corr0; oc[nn][1] *= corr0;
            oc[nn][2] *= corr1; oc[nn][3] *= corr1;
        }

        // ---- O += P V: convert P (C-layout) -> A-layout via quad shuffles ----
        int srcA = (lane & ~3) | (qid >> 1);   // holder of col 8ks+qid
        int srcB = srcA + 2;                   // holder of col 8ks+qid+4
        #pragma unroll
        for (int ks = 0; ks < 8; ks++) {
            float t0 = __shfl_sync(0xffffffffu, sc[ks][0], srcA);
            float t1 = __shfl_sync(0xffffffffu, sc[ks][1], srcA);
            float u0 = __shfl_sync(0xffffffffu, sc[ks][2], srcA);
            float u1 = __shfl_sync(0xffffffffu, sc[ks][3], srcA);
            float w0 = __shfl_sync(0xffffffffu, sc[ks][0], srcB);
            float w1 = __shfl_sync(0xffffffffu, sc[ks][1], srcB);
            float x0 = __shfl_sync(0xffffffffu, sc[ks][2], srcB);
            float x1 = __shfl_sync(0xffffffffu, sc[ks][3], srcB);
            uint32_t a0 = f2tf32((qid & 1) ? t1 : t0);
            uint32_t a1 = f2tf32((qid & 1) ? u1 : u0);
            uint32_t a2 = f2tf32((qid & 1) ? w1 : w0);
            uint32_t a3 = f2tf32((qid & 1) ? x1 : x0);
            #pragma unroll
            for (int nn = 0; nn < 8; nn++) {
                uint32_t b0 = f2tf32(Vs[8 * ks + qid][8 * nn + grp]);
                uint32_t b1 = f2tf32(Vs[8 * ks + qid + 4][8 * nn + grp]);
                MMA_TF32(oc[nn][0], oc[nn][1], oc[nn][2], oc[nn][3],
                         a0, a1, a2, a3, b0, b1);
            }
        }
    }

    float inv0 = 1.f / l0, inv1 = 1.f / l1;
    float* o0 = O + headoff + (size_t)r0 * D_MODEL;
    float* o1 = O + headoff + (size_t)r1 * D_MODEL;
    #pragma unroll
    for (int nn = 0; nn < 8; nn++) {
        int col = 8 * nn + 2 * qid;
        *(float2*)(o0 + col) = make_float2(oc[nn][0] * inv0, oc[nn][1] * inv0);
        *(float2*)(o1 + col) = make_float2(oc[nn][2] * inv1, oc[nn][3] * inv1);
    }
}

// ---------------- h = silu(a) * g (float4) ----------------
__global__ void silumul_kernel(float* a, const float* g, int n4) {
    int i = blockIdx.x * blockDim.x + threadIdx.x;
    if (i >= n4) return;
    float4 av = ((const float4*)a)[i];
    float4 gv = ((const float4*)g)[i];
    av.x = av.x / (1.f + __expf(-av.x)) * gv.x;
    av.y = av.y / (1.f + __expf(-av.y)) * gv.y;
    av.z = av.z / (1.f + __expf(-av.z)) * gv.z;
    av.w = av.w / (1.f + __expf(-av.w)) * gv.w;
    ((float4*)a)[i] = av;
}

// ---------------- launch ----------------
extern "C" void kernel_launch(void* const* d_in, const int* in_sizes, int n_in,
                              void* d_out, int out_size) {
    const float* x    = (const float*)d_in[0];
    const int*   pos  = (const int*)  d_in[1];
    const float* n1w  = (const float*)d_in[2];
    const float* n2w  = (const float*)d_in[3];
    const float* wq   = (const float*)d_in[4];
    const float* wk   = (const float*)d_in[5];
    const float* wv   = (const float*)d_in[6];
    const float* wo   = (const float*)d_in[7];
    const float* w1   = (const float*)d_in[8];
    const float* w2   = (const float*)d_in[9];
    const float* w3   = (const float*)d_in[10];
    float* out = (float*)d_out;

    float *xn, *q, *k, *v, *q2, *k2, *attn, *a, *g;
    cudaGetSymbolAddress((void**)&xn,   g_xn);
    cudaGetSymbolAddress((void**)&q,    g_q);
    cudaGetSymbolAddress((void**)&k,    g_k);
    cudaGetSymbolAddress((void**)&v,    g_v);
    cudaGetSymbolAddress((void**)&q2,   g_q2);
    cudaGetSymbolAddress((void**)&k2,   g_k2);
    cudaGetSymbolAddress((void**)&attn, g_attn);
    cudaGetSymbolAddress((void**)&a,    g_a);
    cudaGetSymbolAddress((void**)&g,    g_g);

    // 1) xn = rmsnorm(x, norm1_w)
    rmsnorm_kernel<<<MROWS, 256>>>(x, n1w, xn);

    // 2) q/k/v projections (tf32 tensor cores)
    dim3 gD(D_MODEL / 128, MROWS / 128);
    mma_tf32_nt_kernel<<<gD, 256>>>(xn, wq, nullptr, q, MROWS, D_MODEL, D_MODEL);
    mma_tf32_nt_kernel<<<gD, 256>>>(xn, wk, nullptr, k, MROWS, D_MODEL, D_MODEL);
    mma_tf32_nt_kernel<<<gD, 256>>>(xn, wv, nullptr, v, MROWS, D_MODEL, D_MODEL);

    // 3) RoPE (out-of-place, fp64 angles)
    rope_dbl_kernel<<<MROWS, 512>>>(q, k, q2, k2, pos);

    // 4) tensor-core causal flash attention
    attn_mma_kernel<<<dim3(SEQ / 128, HEADS, BATCH), 256>>>(q2, k2, v, attn);

    // 5) out = x + attn @ wo^T
    mma_tf32_nt_kernel<<<gD, 256>>>(attn, wo, x, out, MROWS, D_MODEL, D_MODEL);

    // 6) xn = rmsnorm(out, norm2_w)
    rmsnorm_kernel<<<MROWS, 256>>>(out, n2w, xn);

    // 7) a = xn @ w1^T ; g = xn @ w3^T
    dim3 gF(DFF / 128, MROWS / 128);
    mma_tf32_nt_kernel<<<gF, 256>>>(xn, w1, nullptr, a, MROWS, DFF, D_MODEL);
    mma_tf32_nt_kernel<<<gF, 256>>>(xn, w3, nullptr, g, MROWS, DFF, D_MODEL);

    // 8) a = silu(a) * g
    int n4 = MROWS * DFF / 4;
    silumul_kernel<<<(n4 + 255) / 256, 256>>>(a, g, n4);

    // 9) out = out + a @ w2^T   (R == C aliasing legal: no restrict)
    mma_tf32_nt_kernel<<<gD, 256>>>(a, w2, out, out, MROWS, D_MODEL, DFF);
}

// round 13
// speedup vs baseline: 4.5598x; 1.1187x over previous
#include <cuda_runtime.h>
#include <math.h>
#include <stdint.h>

#define D_MODEL 1024
#define SEQ     2048
#define BATCH   2
#define HEADS   16
#define DK      64
#define DFF     4096
#define MROWS   (BATCH * SEQ)   // 4096

// ---------------- scratch (static device allocations) ----------------
__device__ float g_xn  [MROWS * D_MODEL];
__device__ float g_q   [MROWS * D_MODEL];
__device__ float g_k   [MROWS * D_MODEL];
__device__ float g_v   [MROWS * D_MODEL];
__device__ float g_q2  [MROWS * D_MODEL];
__device__ float g_k2  [MROWS * D_MODEL];
__device__ float g_attn[MROWS * D_MODEL];
__device__ float g_a   [(size_t)MROWS * DFF];
__device__ float g_g   [(size_t)MROWS * DFF];

__device__ __forceinline__ uint32_t f2tf32(float f) {
    uint32_t u;
    asm("cvt.rna.tf32.f32 %0, %1;" : "=r"(u) : "f"(f));
    return u;
}

__device__ __forceinline__ uint32_t smem_u32(const void* p) {
    return (uint32_t)__cvta_generic_to_shared(p);
}

#define CP_ASYNC16(dst, src) \
    asm volatile("cp.async.ca.shared.global [%0], [%1], 16;\n" :: "r"(dst), "l"(src))
#define CP_COMMIT() asm volatile("cp.async.commit_group;\n" ::: "memory")
#define CP_WAIT(n)  asm volatile("cp.async.wait_group %0;\n" :: "n"(n) : "memory")

#define MMA_TF32(c0,c1,c2,c3,a0,a1,a2,a3,b0,b1)                         \
    asm volatile(                                                        \
        "mma.sync.aligned.m16n8k8.row.col.f32.tf32.tf32.f32 "           \
        "{%0,%1,%2,%3}, {%4,%5,%6,%7}, {%8,%9}, {%0,%1,%2,%3};"         \
        : "+f"(c0), "+f"(c1), "+f"(c2), "+f"(c3)                         \
        : "r"(a0), "r"(a1), "r"(a2), "r"(a3), "r"(b0), "r"(b1))

// ---------------- RMSNorm ----------------
__global__ void rmsnorm_kernel(const float* __restrict__ x,
                               const float* __restrict__ w,
                               float* __restrict__ o) {
    int row = blockIdx.x;
    const float* xr = x + (size_t)row * D_MODEL;
    float* orow = o + (size_t)row * D_MODEL;
    int tid = threadIdx.x;

    float s = 0.f;
    #pragma unroll
    for (int i = tid; i < D_MODEL; i += 256) {
        float v = xr[i];
        s += v * v;
    }
    #pragma unroll
    for (int off = 16; off > 0; off >>= 1)
        s += __shfl_xor_sync(0xffffffffu, s, off);
    __shared__ float red[8];
    if ((tid & 31) == 0) red[tid >> 5] = s;
    __syncthreads();
    if (tid < 32) {
        float v = (tid < 8) ? red[tid] : 0.f;
        #pragma unroll
        for (int off = 4; off > 0; off >>= 1)
            v += __shfl_xor_sync(0xffffffffu, v, off);
        if (tid == 0) red[0] = v;
    }
    __syncthreads();
    float inv = rsqrtf(red[0] * (1.0f / D_MODEL) + 1e-5f);
    #pragma unroll
    for (int i = tid; i < D_MODEL; i += 256)
        orow[i] = xr[i] * inv * w[i];
}

// ---------------- TF32 tensor-core GEMM (NT), cp.async double-buffered ----------------
// BM=BN=128, BK=16, 256 threads = 8 warps (2m x 4n), warp tile 64x32.
// 2-stage cp.async pipeline; smem row stride 20 floats (conflict-free).
// R/C deliberately NOT __restrict__ (final FFN GEMM passes R==C==d_out).
__global__ __launch_bounds__(256, 2) void mma_tf32_nt_kernel(
    const float* __restrict__ A, const float* __restrict__ B,
    const float* R, float* C, int M, int N, int K) {
    __shared__ float As[2][128 * 20];
    __shared__ float Bs[2][128 * 20];

    int tid  = threadIdx.x;
    int wid  = tid >> 5;
    int lane = tid & 31;
    int grp  = lane >> 2;
    int qid  = lane & 3;

    int wm = (wid & 1) * 64;
    int wn = (wid >> 1) * 32;

    int bx = blockIdx.x;
    int by = blockIdx.y;

    // staging coords: thread stages rows rs and rs+64, k-quad kqs
    int rs  = tid >> 2;          // 0..63
    int kqs = (tid & 3) * 4;     // 0,4,8,12

    const float* Abase = A + (size_t)(by * 128 + rs) * K + kqs;
    const float* Bbase = B + (size_t)(bx * 128 + rs) * K + kqs;
    uint32_t sa0 = smem_u32(&As[0][rs * 20 + kqs]);
    uint32_t sa1 = smem_u32(&As[0][(rs + 64) * 20 + kqs]);
    uint32_t sb0 = smem_u32(&Bs[0][rs * 20 + kqs]);
    uint32_t sb1 = smem_u32(&Bs[0][(rs + 64) * 20 + kqs]);
    const uint32_t bufB = 128 * 20 * 4;   // byte offset between buffers

    float c[4][4][4];
    #pragma unroll
    for (int mt = 0; mt < 4; mt++)
        #pragma unroll
        for (int nt = 0; nt < 4; nt++)
            #pragma unroll
            for (int i = 0; i < 4; i++) c[mt][nt][i] = 0.f;

    int T = K / 16;

    // prefetch tile 0 into buffer 0
    CP_ASYNC16(sa0, Abase);
    CP_ASYNC16(sa1, Abase + (size_t)64 * K);
    CP_ASYNC16(sb0, Bbase);
    CP_ASYNC16(sb1, Bbase + (size_t)64 * K);
    CP_COMMIT();

    for (int t = 0; t < T; t++) {
        if (t + 1 < T) {
            int k0 = (t + 1) * 16;
            uint32_t off = ((t + 1) & 1) * bufB;
            CP_ASYNC16(sa0 + off, Abase + k0);
            CP_ASYNC16(sa1 + off, Abase + (size_t)64 * K + k0);
            CP_ASYNC16(sb0 + off, Bbase + k0);
            CP_ASYNC16(sb1 + off, Bbase + (size_t)64 * K + k0);
            CP_COMMIT();
            CP_WAIT(1);
        } else {
            CP_WAIT(0);
        }
        __syncthreads();

        const float* Asb = As[t & 1];
        const float* Bsb = Bs[t & 1];

        #pragma unroll
        for (int kk = 0; kk < 16; kk += 8) {
            uint32_t af[4][4], bf[4][2];
            #pragma unroll
            for (int mt = 0; mt < 4; mt++) {
                int r0 = wm + mt * 16 + grp;
                af[mt][0] = f2tf32(Asb[r0 * 20 + kk + qid]);
                af[mt][1] = f2tf32(Asb[(r0 + 8) * 20 + kk + qid]);
                af[mt][2] = f2tf32(Asb[r0 * 20 + kk + qid + 4]);
                af[mt][3] = f2tf32(Asb[(r0 + 8) * 20 + kk + qid + 4]);
            }
            #pragma unroll
            for (int nt = 0; nt < 4; nt++) {
                int n0 = wn + nt * 8 + grp;
                bf[nt][0] = f2tf32(Bsb[n0 * 20 + kk + qid]);
                bf[nt][1] = f2tf32(Bsb[n0 * 20 + kk + qid + 4]);
            }
            #pragma unroll
            for (int mt = 0; mt < 4; mt++)
                #pragma unroll
                for (int nt = 0; nt < 4; nt++)
                    MMA_TF32(c[mt][nt][0], c[mt][nt][1], c[mt][nt][2], c[mt][nt][3],
                             af[mt][0], af[mt][1], af[mt][2], af[mt][3],
                             bf[nt][0], bf[nt][1]);
        }
        __syncthreads();
    }

    #pragma unroll
    for (int mt = 0; mt < 4; mt++) {
        int row = by * 128 + wm + mt * 16 + grp;
        #pragma unroll
        for (int nt = 0; nt < 4; nt++) {
            int col = bx * 128 + wn + nt * 8 + qid * 2;
            size_t i0 = (size_t)row * N + col;
            size_t i1 = (size_t)(row + 8) * N + col;
            float v00 = c[mt][nt][0], v01 = c[mt][nt][1];
            float v10 = c[mt][nt][2], v11 = c[mt][nt][3];
            if (R) {
                v00 += R[i0]; v01 += R[i0 + 1];
                v10 += R[i1]; v11 += R[i1 + 1];
            }
            *(float2*)(C + i0) = make_float2(v00, v01);
            *(float2*)(C + i1) = make_float2(v10, v11);
        }
    }
}

// ---------------- RoPE (double precision, out-of-place; validated) ----------------
__global__ void rope_dbl_kernel(const float* __restrict__ qin,
                                const float* __restrict__ kin,
                                float* __restrict__ qout,
                                float* __restrict__ kout,
                                const int* __restrict__ pos) {
    int bs = blockIdx.x;
    int h  = threadIdx.x >> 5;
    int i  = threadIdx.x & 31;
    int p  = pos[bs];

    double freq = exp(-((double)(2 * i) / 64.0) * log(10000.0));
    double ang = (double)p * freq;
    double cd, sd;
    sincos(ang, &sd, &cd);
    float c = (float)cd, s = (float)sd;

    size_t base = (size_t)bs * D_MODEL + h * DK + 2 * i;
    float qe = qin[base], qo = qin[base + 1];
    qout[base]     = qe * c - qo * s;
    qout[base + 1] = qe * s + qo * c;
    float ke = kin[base], ko = kin[base + 1];
    kout[base]     = ke * c - ko * s;
    kout[base + 1] = ke * s + ko * c;
}

// ---------------- Tensor-core causal flash attention (tf32 mma) ----------------
__global__ __launch_bounds__(256) void attn_mma_kernel(
    const float* __restrict__ Q, const float* __restrict__ K,
    const float* __restrict__ V, float* __restrict__ O) {
    __shared__ float Ks[64][68];
    __shared__ float Vs[64][68];

    int tid  = threadIdx.x;
    int wid  = tid >> 5;
    int lane = tid & 31;
    int grp  = lane >> 2;
    int qid  = lane & 3;

    int q0 = blockIdx.x * 128;
    int h  = blockIdx.y;
    int b  = blockIdx.z;

    int r0 = q0 + wid * 16 + grp;
    int r1 = r0 + 8;
    size_t headoff = (size_t)b * SEQ * D_MODEL + h * DK;

    uint32_t qa[8][4];
    {
        const float* q0p = Q + headoff + (size_t)r0 * D_MODEL;
        const float* q1p = Q + headoff + (size_t)r1 * D_MODEL;
        #pragma unroll
        for (int ks = 0; ks < 8; ks++) {
            qa[ks][0] = f2tf32(q0p[8 * ks + qid]);
            qa[ks][1] = f2tf32(q1p[8 * ks + qid]);
            qa[ks][2] = f2tf32(q0p[8 * ks + qid + 4]);
            qa[ks][3] = f2tf32(q1p[8 * ks + qid + 4]);
        }
    }

    float oc[8][4];
    #pragma unroll
    for (int nn = 0; nn < 8; nn++)
        #pragma unroll
        for (int i = 0; i < 4; i++) oc[nn][i] = 0.f;
    float m0 = -INFINITY, m1 = -INFINITY, l0 = 0.f, l1 = 0.f;
    const float scale = 0.125f;

    for (int kv = 0; kv < q0 + 128; kv += 64) {
        __syncthreads();
        for (int idx = tid; idx < 64 * 16; idx += 256) {
            int r = idx >> 4, c = (idx & 15) * 4;
            *(float4*)&Ks[r][c] =
                *(const float4*)(K + headoff + (size_t)(kv + r) * D_MODEL + c);
            *(float4*)&Vs[r][c] =
                *(const float4*)(V + headoff + (size_t)(kv + r) * D_MODEL + c);
        }
        __syncthreads();

        float sc[8][4];
        #pragma unroll
        for (int nn = 0; nn < 8; nn++) {
            sc[nn][0] = sc[nn][1] = sc[nn][2] = sc[nn][3] = 0.f;
            #pragma unroll
            for (int ks = 0; ks < 8; ks++) {
                uint32_t b0 = f2tf32(Ks[8 * nn + grp][8 * ks + qid]);
                uint32_t b1 = f2tf32(Ks[8 * nn + grp][8 * ks + qid + 4]);
                MMA_TF32(sc[nn][0], sc[nn][1], sc[nn][2], sc[nn][3],
                         qa[ks][0], qa[ks][1], qa[ks][2], qa[ks][3], b0, b1);
            }
        }

        #pragma unroll
        for (int nn = 0; nn < 8; nn++) {
            int col = kv + 8 * nn + 2 * qid;
            sc[nn][0] = (col     <= r0) ? sc[nn][0] * scale : -INFINITY;
            sc[nn][1] = (col + 1 <= r0) ? sc[nn][1] * scale : -INFINITY;
            sc[nn][2] = (col     <= r1) ? sc[nn][2] * scale : -INFINITY;
            sc[nn][3] = (col + 1 <= r1) ? sc[nn][3] * scale : -INFINITY;
        }

        float tm0 = -INFINITY, tm1 = -INFINITY;
        #pragma unroll
        for (int nn = 0; nn < 8; nn++) {
            tm0 = fmaxf(tm0, fmaxf(sc[nn][0], sc[nn][1]));
            tm1 = fmaxf(tm1, fmaxf(sc[nn][2], sc[nn][3]));
        }
        tm0 = fmaxf(tm0, __shfl_xor_sync(0xffffffffu, tm0, 1));
        tm0 = fmaxf(tm0, __shfl_xor_sync(0xffffffffu, tm0, 2));
        tm1 = fmaxf(tm1, __shfl_xor_sync(0xffffffffu, tm1, 1));
        tm1 = fmaxf(tm1, __shfl_xor_sync(0xffffffffu, tm1, 2));

        float nm0 = fmaxf(m0, tm0), nm1 = fmaxf(m1, tm1);
        float corr0 = __expf(m0 - nm0), corr1 = __expf(m1 - nm1);
        m0 = nm0; m1 = nm1;

        float sum0 = 0.f, sum1 = 0.f;
        #pragma unroll
        for (int nn = 0; nn < 8; nn++) {
            sc[nn][0] = __expf(sc[nn][0] - nm0);
            sc[nn][1] = __expf(sc[nn][1] - nm0);
            sc[nn][2] = __expf(sc[nn][2] - nm1);
            sc[nn][3] = __expf(sc[nn][3] - nm1);
            sum0 += sc[nn][0] + sc[nn][1];
            sum1 += sc[nn][2] + sc[nn][3];
        }
        sum0 += __shfl_xor_sync(0xffffffffu, sum0, 1);
        sum0 += __shfl_xor_sync(0xffffffffu, sum0, 2);
        sum1 += __shfl_xor_sync(0xffffffffu, sum1, 1);
        sum1 += __shfl_xor_sync(0xffffffffu, sum1, 2);
        l0 = l0 * corr0 + sum0;
        l1 = l1 * corr1 + sum1;

        #pragma unroll
        for (int nn = 0; nn < 8; nn++) {
            oc[nn][0] *= corr0; oc[nn][1] *= corr0;
            oc[nn][2] *= corr1; oc[nn][3] *= corr1;
        }

        int srcA = (lane & ~3) | (qid >> 1);
        int srcB = srcA + 2;
        #pragma unroll
        for (int ks = 0; ks < 8; ks++) {
            float t0 = __shfl_sync(0xffffffffu, sc[ks][0], srcA);
            float t1 = __shfl_sync(0xffffffffu, sc[ks][1], srcA);
            float u0 = __shfl_sync(0xffffffffu, sc[ks][2], srcA);
            float u1 = __shfl_sync(0xffffffffu, sc[ks][3], srcA);
            float w0 = __shfl_sync(0xffffffffu, sc[ks][0], srcB);
            float w1 = __shfl_sync(0xffffffffu, sc[ks][1], srcB);
            float x0 = __shfl_sync(0xffffffffu, sc[ks][2], srcB);
            float x1 = __shfl_sync(0xffffffffu, sc[ks][3], srcB);
            uint32_t a0 = f2tf32((qid & 1) ? t1 : t0);
            uint32_t a1 = f2tf32((qid & 1) ? u1 : u0);
            uint32_t a2 = f2tf32((qid & 1) ? w1 : w0);
            uint32_t a3 = f2tf32((qid & 1) ? x1 : x0);
            #pragma unroll
            for (int nn = 0; nn < 8; nn++) {
                uint32_t b0 = f2tf32(Vs[8 * ks + qid][8 * nn + grp]);
                uint32_t b1 = f2tf32(Vs[8 * ks + qid + 4][8 * nn + grp]);
                MMA_TF32(oc[nn][0], oc[nn][1], oc[nn][2], oc[nn][3],
                         a0, a1, a2, a3, b0, b1);
            }
        }
    }

    float inv0 = 1.f / l0, inv1 = 1.f / l1;
    float* o0 = O + headoff + (size_t)r0 * D_MODEL;
    float* o1 = O + headoff + (size_t)r1 * D_MODEL;
    #pragma unroll
    for (int nn = 0; nn < 8; nn++) {
        int col = 8 * nn + 2 * qid;
        *(float2*)(o0 + col) = make_float2(oc[nn][0] * inv0, oc[nn][1] * inv0);
        *(float2*)(o1 + col) = make_float2(oc[nn][2] * inv1, oc[nn][3] * inv1);
    }
}

// ---------------- h = silu(a) * g (float4) ----------------
__global__ void silumul_kernel(float* a, const float* g, int n4) {
    int i = blockIdx.x * blockDim.x + threadIdx.x;
    if (i >= n4) return;
    float4 av = ((const float4*)a)[i];
    float4 gv = ((const float4*)g)[i];
    av.x = av.x / (1.f + __expf(-av.x)) * gv.x;
    av.y = av.y / (1.f + __expf(-av.y)) * gv.y;
    av.z = av.z / (1.f + __expf(-av.z)) * gv.z;
    av.w = av.w / (1.f + __expf(-av.w)) * gv.w;
    ((float4*)a)[i] = av;
}

// ---------------- launch ----------------
extern "C" void kernel_launch(void* const* d_in, const int* in_sizes, int n_in,
                              void* d_out, int out_size) {
    const float* x    = (const float*)d_in[0];
    const int*   pos  = (const int*)  d_in[1];
    const float* n1w  = (const float*)d_in[2];
    const float* n2w  = (const float*)d_in[3];
    const float* wq   = (const float*)d_in[4];
    const float* wk   = (const float*)d_in[5];
    const float* wv   = (const float*)d_in[6];
    const float* wo   = (const float*)d_in[7];
    const float* w1   = (const float*)d_in[8];
    const float* w2   = (const float*)d_in[9];
    const float* w3   = (const float*)d_in[10];
    float* out = (float*)d_out;

    float *xn, *q, *k, *v, *q2, *k2, *attn, *a, *g;
    cudaGetSymbolAddress((void**)&xn,   g_xn);
    cudaGetSymbolAddress((void**)&q,    g_q);
    cudaGetSymbolAddress((void**)&k,    g_k);
    cudaGetSymbolAddress((void**)&v,    g_v);
    cudaGetSymbolAddress((void**)&q2,   g_q2);
    cudaGetSymbolAddress((void**)&k2,   g_k2);
    cudaGetSymbolAddress((void**)&attn, g_attn);
    cudaGetSymbolAddress((void**)&a,    g_a);
    cudaGetSymbolAddress((void**)&g,    g_g);

    // 1) xn = rmsnorm(x, norm1_w)
    rmsnorm_kernel<<<MROWS, 256>>>(x, n1w, xn);

    // 2) q/k/v projections (tf32 tensor cores, pipelined)
    dim3 gD(D_MODEL / 128, MROWS / 128);
    mma_tf32_nt_kernel<<<gD, 256>>>(xn, wq, nullptr, q, MROWS, D_MODEL, D_MODEL);
    mma_tf32_nt_kernel<<<gD, 256>>>(xn, wk, nullptr, k, MROWS, D_MODEL, D_MODEL);
    mma_tf32_nt_kernel<<<gD, 256>>>(xn, wv, nullptr, v, MROWS, D_MODEL, D_MODEL);

    // 3) RoPE (out-of-place, fp64 angles)
    rope_dbl_kernel<<<MROWS, 512>>>(q, k, q2, k2, pos);

    // 4) tensor-core causal flash attention
    attn_mma_kernel<<<dim3(SEQ / 128, HEADS, BATCH), 256>>>(q2, k2, v, attn);

    // 5) out = x + attn @ wo^T
    mma_tf32_nt_kernel<<<gD, 256>>>(attn, wo, x, out, MROWS, D_MODEL, D_MODEL);

    // 6) xn = rmsnorm(out, norm2_w)
    rmsnorm_kernel<<<MROWS, 256>>>(out, n2w, xn);

    // 7) a = xn @ w1^T ; g = xn @ w3^T
    dim3 gF(DFF / 128, MROWS / 128);
    mma_tf32_nt_kernel<<<gF, 256>>>(xn, w1, nullptr, a, MROWS, DFF, D_MODEL);
    mma_tf32_nt_kernel<<<gF, 256>>>(xn, w3, nullptr, g, MROWS, DFF, D_MODEL);

    // 8) a = silu(a) * g
    int n4 = MROWS * DFF / 4;
    silumul_kernel<<<(n4 + 255) / 256, 256>>>(a, g, n4);

    // 9) out = out + a @ w2^T   (R == C aliasing legal: no restrict)
    mma_tf32_nt_kernel<<<gD, 256>>>(a, w2, out, out, MROWS, D_MODEL, DFF);
}

// round 14
// speedup vs baseline: 4.6390x; 1.0174x over previous
#include <cuda_runtime.h>
#include <math.h>
#include <stdint.h>

#define D_MODEL 1024
#define SEQ     2048
#define BATCH   2
#define HEADS   16
#define DK      64
#define DFF     4096
#define MROWS   (BATCH * SEQ)   // 4096

// ---------------- scratch (static device allocations) ----------------
__device__ float g_xn  [MROWS * D_MODEL];
__device__ float g_q   [MROWS * D_MODEL];
__device__ float g_k   [MROWS * D_MODEL];
__device__ float g_v   [MROWS * D_MODEL];
__device__ float g_q2  [MROWS * D_MODEL];
__device__ float g_k2  [MROWS * D_MODEL];
__device__ float g_attn[MROWS * D_MODEL];
__device__ float g_a   [(size_t)MROWS * DFF];
__device__ float g_g   [(size_t)MROWS * DFF];
__device__ float g_wr4 [4 * 1048576];   // rounded wq, wk, wv, wo
__device__ float g_wrf [3 * 4194304];   // rounded w1, w2, w3

__device__ __forceinline__ uint32_t f2tf32(float f) {
    uint32_t u;
    asm("cvt.rna.tf32.f32 %0, %1;" : "=r"(u) : "f"(f));
    return u;
}
__device__ __forceinline__ float rtf32(float f) {
    return __uint_as_float(f2tf32(f));
}
__device__ __forceinline__ uint32_t smem_u32(const void* p) {
    return (uint32_t)__cvta_generic_to_shared(p);
}

#define CP_ASYNC16(dst, src) \
    asm volatile("cp.async.ca.shared.global [%0], [%1], 16;\n" :: "r"(dst), "l"(src))
#define CP_COMMIT() asm volatile("cp.async.commit_group;\n" ::: "memory")
#define CP_WAIT(n)  asm volatile("cp.async.wait_group %0;\n" :: "n"(n) : "memory")

#define MMA_TF32(c0,c1,c2,c3,a0,a1,a2,a3,b0,b1)                         \
    asm volatile(                                                        \
        "mma.sync.aligned.m16n8k8.row.col.f32.tf32.tf32.f32 "           \
        "{%0,%1,%2,%3}, {%4,%5,%6,%7}, {%8,%9}, {%0,%1,%2,%3};"         \
        : "+f"(c0), "+f"(c1), "+f"(c2), "+f"(c3)                         \
        : "r"(a0), "r"(a1), "r"(a2), "r"(a3), "r"(b0), "r"(b1))

// ---------------- round a buffer to tf32 (for weights) ----------------
__global__ void round_tf32_kernel(float* __restrict__ dst,
                                  const float* __restrict__ src, int n4) {
    int i = blockIdx.x * blockDim.x + threadIdx.x;
    if (i >= n4) return;
    float4 v = ((const float4*)src)[i];
    v.x = rtf32(v.x); v.y = rtf32(v.y); v.z = rtf32(v.z); v.w = rtf32(v.w);
    ((float4*)dst)[i] = v;
}

// ---------------- RMSNorm (emits tf32-rounded output) ----------------
__global__ void rmsnorm_kernel(const float* __restrict__ x,
                               const float* __restrict__ w,
                               float* __restrict__ o) {
    int row = blockIdx.x;
    const float* xr = x + (size_t)row * D_MODEL;
    float* orow = o + (size_t)row * D_MODEL;
    int tid = threadIdx.x;

    float s = 0.f;
    #pragma unroll
    for (int i = tid; i < D_MODEL; i += 256) {
        float v = xr[i];
        s += v * v;
    }
    #pragma unroll
    for (int off = 16; off > 0; off >>= 1)
        s += __shfl_xor_sync(0xffffffffu, s, off);
    __shared__ float red[8];
    if ((tid & 31) == 0) red[tid >> 5] = s;
    __syncthreads();
    if (tid < 32) {
        float v = (tid < 8) ? red[tid] : 0.f;
        #pragma unroll
        for (int off = 4; off > 0; off >>= 1)
            v += __shfl_xor_sync(0xffffffffu, v, off);
        if (tid == 0) red[0] = v;
    }
    __syncthreads();
    float inv = rsqrtf(red[0] * (1.0f / D_MODEL) + 1e-5f);
    #pragma unroll
    for (int i = tid; i < D_MODEL; i += 256)
        orow[i] = rtf32(xr[i] * inv * w[i]);
}

// ---------------- TF32 GEMM (NT), 4 warps x 64x64 tiles, cp.async 2-stage ----------------
// Inputs assumed pre-rounded to tf32 -> raw-bit mma operands.
// R/C NOT __restrict__ (final FFN GEMM passes R==C==d_out).
__global__ __launch_bounds__(128, 2) void mma_tf32_nt_kernel(
    const float* __restrict__ A, const float* __restrict__ B,
    const float* R, float* C, int M, int N, int K, int roundC) {
    __shared__ float As[2][128 * 20];
    __shared__ float Bs[2][128 * 20];

    int tid  = threadIdx.x;
    int wid  = tid >> 5;
    int lane = tid & 31;
    int grp  = lane >> 2;
    int qid  = lane & 3;

    int wm = (wid & 1) * 64;
    int wn = (wid >> 1) * 64;

    int bx = blockIdx.x;
    int by = blockIdx.y;

    int rs  = tid >> 2;          // 0..31
    int kqs = (tid & 3) * 4;

    const float* Abase = A + (size_t)(by * 128 + rs) * K + kqs;
    const float* Bbase = B + (size_t)(bx * 128 + rs) * K + kqs;
    uint32_t sa[4], sb[4];
    #pragma unroll
    for (int i = 0; i < 4; i++) {
        sa[i] = smem_u32(&As[0][(rs + 32 * i) * 20 + kqs]);
        sb[i] = smem_u32(&Bs[0][(rs + 32 * i) * 20 + kqs]);
    }
    const uint32_t bufB = 128 * 20 * 4;

    float c[4][8][4];
    #pragma unroll
    for (int mt = 0; mt < 4; mt++)
        #pragma unroll
        for (int nt = 0; nt < 8; nt++)
            #pragma unroll
            for (int i = 0; i < 4; i++) c[mt][nt][i] = 0.f;

    int T = K / 16;

    #pragma unroll
    for (int i = 0; i < 4; i++) {
        CP_ASYNC16(sa[i], Abase + (size_t)(32 * i) * K);
        CP_ASYNC16(sb[i], Bbase + (size_t)(32 * i) * K);
    }
    CP_COMMIT();

    for (int t = 0; t < T; t++) {
        if (t + 1 < T) {
            int k0 = (t + 1) * 16;
            uint32_t off = ((t + 1) & 1) * bufB;
            #pragma unroll
            for (int i = 0; i < 4; i++) {
                CP_ASYNC16(sa[i] + off, Abase + (size_t)(32 * i) * K + k0);
                CP_ASYNC16(sb[i] + off, Bbase + (size_t)(32 * i) * K + k0);
            }
            CP_COMMIT();
            CP_WAIT(1);
        } else {
            CP_WAIT(0);
        }
        __syncthreads();

        const float* Asb = As[t & 1];
        const float* Bsb = Bs[t & 1];

        #pragma unroll
        for (int kk = 0; kk < 16; kk += 8) {
            uint32_t af[4][4], bf[8][2];
            #pragma unroll
            for (int mt = 0; mt < 4; mt++) {
                int r0 = wm + mt * 16 + grp;
                af[mt][0] = __float_as_uint(Asb[r0 * 20 + kk + qid]);
                af[mt][1] = __float_as_uint(Asb[(r0 + 8) * 20 + kk + qid]);
                af[mt][2] = __float_as_uint(Asb[r0 * 20 + kk + qid + 4]);
                af[mt][3] = __float_as_uint(Asb[(r0 + 8) * 20 + kk + qid + 4]);
            }
            #pragma unroll
            for (int nt = 0; nt < 8; nt++) {
                int n0 = wn + nt * 8 + grp;
                bf[nt][0] = __float_as_uint(Bsb[n0 * 20 + kk + qid]);
                bf[nt][1] = __float_as_uint(Bsb[n0 * 20 + kk + qid + 4]);
            }
            #pragma unroll
            for (int mt = 0; mt < 4; mt++)
                #pragma unroll
                for (int nt = 0; nt < 8; nt++)
                    MMA_TF32(c[mt][nt][0], c[mt][nt][1], c[mt][nt][2], c[mt][nt][3],
                             af[mt][0], af[mt][1], af[mt][2], af[mt][3],
                             bf[nt][0], bf[nt][1]);
        }
        __syncthreads();
    }

    #pragma unroll
    for (int mt = 0; mt < 4; mt++) {
        int row = by * 128 + wm + mt * 16 + grp;
        #pragma unroll
        for (int nt = 0; nt < 8; nt++) {
            int col = bx * 128 + wn + nt * 8 + qid * 2;
            size_t i0 = (size_t)row * N + col;
            size_t i1 = (size_t)(row + 8) * N + col;
            float v00 = c[mt][nt][0], v01 = c[mt][nt][1];
            float v10 = c[mt][nt][2], v11 = c[mt][nt][3];
            if (R) {
                v00 += R[i0]; v01 += R[i0 + 1];
                v10 += R[i1]; v11 += R[i1 + 1];
            }
            if (roundC) {
                v00 = rtf32(v00); v01 = rtf32(v01);
                v10 = rtf32(v10); v11 = rtf32(v11);
            }
            *(float2*)(C + i0) = make_float2(v00, v01);
            *(float2*)(C + i1) = make_float2(v10, v11);
        }
    }
}

// ---------------- RoPE (fp64 angles, out-of-place, tf32-rounded outputs) ----------------
__global__ void rope_dbl_kernel(const float* __restrict__ qin,
                                const float* __restrict__ kin,
                                float* __restrict__ qout,
                                float* __restrict__ kout,
                                const int* __restrict__ pos) {
    int bs = blockIdx.x;
    int h  = threadIdx.x >> 5;
    int i  = threadIdx.x & 31;
    int p  = pos[bs];

    double freq = exp(-((double)(2 * i) / 64.0) * log(10000.0));
    double ang = (double)p * freq;
    double cd, sd;
    sincos(ang, &sd, &cd);
    float c = (float)cd, s = (float)sd;

    size_t base = (size_t)bs * D_MODEL + h * DK + 2 * i;
    float qe = qin[base], qo = qin[base + 1];
    qout[base]     = rtf32(qe * c - qo * s);
    qout[base + 1] = rtf32(qe * s + qo * c);
    float ke = kin[base], ko = kin[base + 1];
    kout[base]     = rtf32(ke * c - ko * s);
    kout[base + 1] = rtf32(ke * s + ko * c);
}

// ---------------- Tensor-core causal flash attention (tf32 mma) ----------------
// Q/K/V pre-rounded -> raw-bit operands. O emitted tf32-rounded (feeds wo GEMM).
__global__ __launch_bounds__(256) void attn_mma_kernel(
    const float* __restrict__ Q, const float* __restrict__ K,
    const float* __restrict__ V, float* __restrict__ O) {
    __shared__ float Ks[64][68];
    __shared__ float Vs[64][68];

    int tid  = threadIdx.x;
    int wid  = tid >> 5;
    int lane = tid & 31;
    int grp  = lane >> 2;
    int qid  = lane & 3;

    int q0 = blockIdx.x * 128;
    int h  = blockIdx.y;
    int b  = blockIdx.z;

    int r0 = q0 + wid * 16 + grp;
    int r1 = r0 + 8;
    size_t headoff = (size_t)b * SEQ * D_MODEL + h * DK;

    uint32_t qa[8][4];
    {
        const float* q0p = Q + headoff + (size_t)r0 * D_MODEL;
        const float* q1p = Q + headoff + (size_t)r1 * D_MODEL;
        #pragma unroll
        for (int ks = 0; ks < 8; ks++) {
            qa[ks][0] = __float_as_uint(q0p[8 * ks + qid]);
            qa[ks][1] = __float_as_uint(q1p[8 * ks + qid]);
            qa[ks][2] = __float_as_uint(q0p[8 * ks + qid + 4]);
            qa[ks][3] = __float_as_uint(q1p[8 * ks + qid + 4]);
        }
    }

    float oc[8][4];
    #pragma unroll
    for (int nn = 0; nn < 8; nn++)
        #pragma unroll
        for (int i = 0; i < 4; i++) oc[nn][i] = 0.f;
    float m0 = -INFINITY, m1 = -INFINITY, l0 = 0.f, l1 = 0.f;
    const float scale = 0.125f;

    for (int kv = 0; kv < q0 + 128; kv += 64) {
        __syncthreads();
        for (int idx = tid; idx < 64 * 16; idx += 256) {
            int r = idx >> 4, c = (idx & 15) * 4;
            *(float4*)&Ks[r][c] =
                *(const float4*)(K + headoff + (size_t)(kv + r) * D_MODEL + c);
            *(float4*)&Vs[r][c] =
                *(const float4*)(V + headoff + (size_t)(kv + r) * D_MODEL + c);
        }
        __syncthreads();

        float sc[8][4];
        #pragma unroll
        for (int nn = 0; nn < 8; nn++) {
            sc[nn][0] = sc[nn][1] = sc[nn][2] = sc[nn][3] = 0.f;
            #pragma unroll
            for (int ks = 0; ks < 8; ks++) {
                uint32_t b0 = __float_as_uint(Ks[8 * nn + grp][8 * ks + qid]);
                uint32_t b1 = __float_as_uint(Ks[8 * nn + grp][8 * ks + qid + 4]);
                MMA_TF32(sc[nn][0], sc[nn][1], sc[nn][2], sc[nn][3],
                         qa[ks][0], qa[ks][1], qa[ks][2], qa[ks][3], b0, b1);
            }
        }

        #pragma unroll
        for (int nn = 0; nn < 8; nn++) {
            int col = kv + 8 * nn + 2 * qid;
            sc[nn][0] = (col     <= r0) ? sc[nn][0] * scale : -INFINITY;
            sc[nn][1] = (col + 1 <= r0) ? sc[nn][1] * scale : -INFINITY;
            sc[nn][2] = (col     <= r1) ? sc[nn][2] * scale : -INFINITY;
            sc[nn][3] = (col + 1 <= r1) ? sc[nn][3] * scale : -INFINITY;
        }

        float tm0 = -INFINITY, tm1 = -INFINITY;
        #pragma unroll
        for (int nn = 0; nn < 8; nn++) {
            tm0 = fmaxf(tm0, fmaxf(sc[nn][0], sc[nn][1]));
            tm1 = fmaxf(tm1, fmaxf(sc[nn][2], sc[nn][3]));
        }
        tm0 = fmaxf(tm0, __shfl_xor_sync(0xffffffffu, tm0, 1));
        tm0 = fmaxf(tm0, __shfl_xor_sync(0xffffffffu, tm0, 2));
        tm1 = fmaxf(tm1, __shfl_xor_sync(0xffffffffu, tm1, 1));
        tm1 = fmaxf(tm1, __shfl_xor_sync(0xffffffffu, tm1, 2));

        float nm0 = fmaxf(m0, tm0), nm1 = fmaxf(m1, tm1);
        float corr0 = __expf(m0 - nm0), corr1 = __expf(m1 - nm1);
        m0 = nm0; m1 = nm1;

        float sum0 = 0.f, sum1 = 0.f;
        #pragma unroll
        for (int nn = 0; nn < 8; nn++) {
            sc[nn][0] = __expf(sc[nn][0] - nm0);
            sc[nn][1] = __expf(sc[nn][1] - nm0);
            sc[nn][2] = __expf(sc[nn][2] - nm1);
            sc[nn][3] = __expf(sc[nn][3] - nm1);
            sum0 += sc[nn][0] + sc[nn][1];
            sum1 += sc[nn][2] + sc[nn][3];
        }
        sum0 += __shfl_xor_sync(0xffffffffu, sum0, 1);
        sum0 += __shfl_xor_sync(0xffffffffu, sum0, 2);
        sum1 += __shfl_xor_sync(0xffffffffu, sum1, 1);
        sum1 += __shfl_xor_sync(0xffffffffu, sum1, 2);
        l0 = l0 * corr0 + sum0;
        l1 = l1 * corr1 + sum1;

        #pragma unroll
        for (int nn = 0; nn < 8; nn++) {
            oc[nn][0] *= corr0; oc[nn][1] *= corr0;
            oc[nn][2] *= corr1; oc[nn][3] *= corr1;
        }

        int srcA = (lane & ~3) | (qid >> 1);
        int srcB = srcA + 2;
        #pragma unroll
        for (int ks = 0; ks < 8; ks++) {
            float t0 = __shfl_sync(0xffffffffu, sc[ks][0], srcA);
            float t1 = __shfl_sync(0xffffffffu, sc[ks][1], srcA);
            float u0 = __shfl_sync(0xffffffffu, sc[ks][2], srcA);
            float u1 = __shfl_sync(0xffffffffu, sc[ks][3], srcA);
            float w0 = __shfl_sync(0xffffffffu, sc[ks][0], srcB);
            float w1 = __shfl_sync(0xffffffffu, sc[ks][1], srcB);
            float x0 = __shfl_sync(0xffffffffu, sc[ks][2], srcB);
            float x1 = __shfl_sync(0xffffffffu, sc[ks][3], srcB);
            uint32_t a0 = f2tf32((qid & 1) ? t1 : t0);
            uint32_t a1 = f2tf32((qid & 1) ? u1 : u0);
            uint32_t a2 = f2tf32((qid & 1) ? w1 : w0);
            uint32_t a3 = f2tf32((qid & 1) ? x1 : x0);
            #pragma unroll
            for (int nn = 0; nn < 8; nn++) {
                uint32_t b0 = __float_as_uint(Vs[8 * ks + qid][8 * nn + grp]);
                uint32_t b1 = __float_as_uint(Vs[8 * ks + qid + 4][8 * nn + grp]);
                MMA_TF32(oc[nn][0], oc[nn][1], oc[nn][2], oc[nn][3],
                         a0, a1, a2, a3, b0, b1);
            }
        }
    }

    float inv0 = 1.f / l0, inv1 = 1.f / l1;
    float* o0 = O + headoff + (size_t)r0 * D_MODEL;
    float* o1 = O + headoff + (size_t)r1 * D_MODEL;
    #pragma unroll
    for (int nn = 0; nn < 8; nn++) {
        int col = 8 * nn + 2 * qid;
        *(float2*)(o0 + col) = make_float2(rtf32(oc[nn][0] * inv0), rtf32(oc[nn][1] * inv0));
        *(float2*)(o1 + col) = make_float2(rtf32(oc[nn][2] * inv1), rtf32(oc[nn][3] * inv1));
    }
}

// ---------------- h = silu(a) * g, tf32-rounded (feeds w2 GEMM) ----------------
__global__ void silumul_kernel(float* a, const float* g, int n4) {
    int i = blockIdx.x * blockDim.x + threadIdx.x;
    if (i >= n4) return;
    float4 av = ((const float4*)a)[i];
    float4 gv = ((const float4*)g)[i];
    av.x = rtf32(av.x / (1.f + __expf(-av.x)) * gv.x);
    av.y = rtf32(av.y / (1.f + __expf(-av.y)) * gv.y);
    av.z = rtf32(av.z / (1.f + __expf(-av.z)) * gv.z);
    av.w = rtf32(av.w / (1.f + __expf(-av.w)) * gv.w);
    ((float4*)a)[i] = av;
}

// ---------------- launch ----------------
extern "C" void kernel_launch(void* const* d_in, const int* in_sizes, int n_in,
                              void* d_out, int out_size) {
    const float* x    = (const float*)d_in[0];
    const int*   pos  = (const int*)  d_in[1];
    const float* n1w  = (const float*)d_in[2];
    const float* n2w  = (const float*)d_in[3];
    const float* wq   = (const float*)d_in[4];
    const float* wk   = (const float*)d_in[5];
    const float* wv   = (const float*)d_in[6];
    const float* wo   = (const float*)d_in[7];
    const float* w1   = (const float*)d_in[8];
    const float* w2   = (const float*)d_in[9];
    const float* w3   = (const float*)d_in[10];
    float* out = (float*)d_out;

    float *xn, *q, *k, *v, *q2, *k2, *attn, *a, *g, *wr4, *wrf;
    cudaGetSymbolAddress((void**)&xn,   g_xn);
    cudaGetSymbolAddress((void**)&q,    g_q);
    cudaGetSymbolAddress((void**)&k,    g_k);
    cudaGetSymbolAddress((void**)&v,    g_v);
    cudaGetSymbolAddress((void**)&q2,   g_q2);
    cudaGetSymbolAddress((void**)&k2,   g_k2);
    cudaGetSymbolAddress((void**)&attn, g_attn);
    cudaGetSymbolAddress((void**)&a,    g_a);
    cudaGetSymbolAddress((void**)&g,    g_g);
    cudaGetSymbolAddress((void**)&wr4,  g_wr4);
    cudaGetSymbolAddress((void**)&wrf,  g_wrf);

    float* rwq = wr4;
    float* rwk = wr4 + 1048576;
    float* rwv = wr4 + 2 * 1048576;
    float* rwo = wr4 + 3 * 1048576;
    float* rw1 = wrf;
    float* rw2 = wrf + 4194304;
    float* rw3 = wrf + 2 * 4194304;

    // 0) pre-round weights to tf32
    int nq4 = 1048576 / 4, nf4 = 4194304 / 4;
    round_tf32_kernel<<<(nq4 + 255) / 256, 256>>>(rwq, wq, nq4);
    round_tf32_kernel<<<(nq4 + 255) / 256, 256>>>(rwk, wk, nq4);
    round_tf32_kernel<<<(nq4 + 255) / 256, 256>>>(rwv, wv, nq4);
    round_tf32_kernel<<<(nq4 + 255) / 256, 256>>>(rwo, wo, nq4);
    round_tf32_kernel<<<(nf4 + 255) / 256, 256>>>(rw1, w1, nf4);
    round_tf32_kernel<<<(nf4 + 255) / 256, 256>>>(rw2, w2, nf4);
    round_tf32_kernel<<<(nf4 + 255) / 256, 256>>>(rw3, w3, nf4);

    // 1) xn = rmsnorm(x, norm1_w)  [tf32-rounded]
    rmsnorm_kernel<<<MROWS, 256>>>(x, n1w, xn);

    // 2) q/k/v projections; v rounded (feeds attention V directly)
    dim3 gD(D_MODEL / 128, MROWS / 128);
    mma_tf32_nt_kernel<<<gD, 128>>>(xn, rwq, nullptr, q, MROWS, D_MODEL, D_MODEL, 0);
    mma_tf32_nt_kernel<<<gD, 128>>>(xn, rwk, nullptr, k, MROWS, D_MODEL, D_MODEL, 0);
    mma_tf32_nt_kernel<<<gD, 128>>>(xn, rwv, nullptr, v, MROWS, D_MODEL, D_MODEL, 1);

    // 3) RoPE (tf32-rounded outputs)
    rope_dbl_kernel<<<MROWS, 512>>>(q, k, q2, k2, pos);

    // 4) tensor-core causal flash attention (tf32-rounded O)
    attn_mma_kernel<<<dim3(SEQ / 128, HEADS, BATCH), 256>>>(q2, k2, v, attn);

    // 5) out = x + attn @ wo^T
    mma_tf32_nt_kernel<<<gD, 128>>>(attn, rwo, x, out, MROWS, D_MODEL, D_MODEL, 0);

    // 6) xn = rmsnorm(out, norm2_w)  [tf32-rounded]
    rmsnorm_kernel<<<MROWS, 256>>>(out, n2w, xn);

    // 7) a = xn @ w1^T ; g = xn @ w3^T
    dim3 gF(DFF / 128, MROWS / 128);
    mma_tf32_nt_kernel<<<gF, 128>>>(xn, rw1, nullptr, a, MROWS, DFF, D_MODEL, 0);
    mma_tf32_nt_kernel<<<gF, 128>>>(xn, rw3, nullptr, g, MROWS, DFF, D_MODEL, 0);

    // 8) a = silu(a) * g  [tf32-rounded]
    int n4 = MROWS * DFF / 4;
    silumul_kernel<<<(n4 + 255) / 256, 256>>>(a, g, n4);

    // 9) out = out + a @ w2^T   (R == C aliasing legal: no restrict)
    mma_tf32_nt_kernel<<<gD, 128>>>(a, rw2, out, out, MROWS, D_MODEL, DFF, 0);
}

// round 15
// speedup vs baseline: 4.7323x; 1.0201x over previous
#include <cuda_runtime.h>
#include <math.h>
#include <stdint.h>

#define D_MODEL 1024
#define SEQ     2048
#define BATCH   2
#define HEADS   16
#define DK      64
#define DFF     4096
#define MROWS   (BATCH * SEQ)   // 4096

// ---------------- scratch (static device allocations) ----------------
__device__ float g_xn  [MROWS * D_MODEL];
__device__ float g_q   [MROWS * D_MODEL];
__device__ float g_k   [MROWS * D_MODEL];
__device__ float g_v   [MROWS * D_MODEL];
__device__ float g_q2  [MROWS * D_MODEL];
__device__ float g_k2  [MROWS * D_MODEL];
__device__ float g_attn[MROWS * D_MODEL];
__device__ float g_a   [(size_t)MROWS * DFF];
__device__ float g_g   [(size_t)MROWS * DFF];

__device__ __forceinline__ uint32_t f2tf32(float f) {
    uint32_t u;
    asm("cvt.rna.tf32.f32 %0, %1;" : "=r"(u) : "f"(f));
    return u;
}
__device__ __forceinline__ uint32_t smem_u32(const void* p) {
    return (uint32_t)__cvta_generic_to_shared(p);
}

#define CP_ASYNC16(dst, src) \
    asm volatile("cp.async.ca.shared.global [%0], [%1], 16;\n" :: "r"(dst), "l"(src))
#define CP_COMMIT() asm volatile("cp.async.commit_group;\n" ::: "memory")
#define CP_WAIT(n)  asm volatile("cp.async.wait_group %0;\n" :: "n"(n) : "memory")

#define MMA_TF32(c0,c1,c2,c3,a0,a1,a2,a3,b0,b1)                         \
    asm volatile(                                                        \
        "mma.sync.aligned.m16n8k8.row.col.f32.tf32.tf32.f32 "           \
        "{%0,%1,%2,%3}, {%4,%5,%6,%7}, {%8,%9}, {%0,%1,%2,%3};"         \
        : "+f"(c0), "+f"(c1), "+f"(c2), "+f"(c3)                         \
        : "r"(a0), "r"(a1), "r"(a2), "r"(a3), "r"(b0), "r"(b1))

// ---------------- RMSNorm ----------------
__global__ void rmsnorm_kernel(const float* __restrict__ x,
                               const float* __restrict__ w,
                               float* __restrict__ o) {
    int row = blockIdx.x;
    const float* xr = x + (size_t)row * D_MODEL;
    float* orow = o + (size_t)row * D_MODEL;
    int tid = threadIdx.x;

    float s = 0.f;
    #pragma unroll
    for (int i = tid; i < D_MODEL; i += 256) {
        float v = xr[i];
        s += v * v;
    }
    #pragma unroll
    for (int off = 16; off > 0; off >>= 1)
        s += __shfl_xor_sync(0xffffffffu, s, off);
    __shared__ float red[8];
    if ((tid & 31) == 0) red[tid >> 5] = s;
    __syncthreads();
    if (tid < 32) {
        float v = (tid < 8) ? red[tid] : 0.f;
        #pragma unroll
        for (int off = 4; off > 0; off >>= 1)
            v += __shfl_xor_sync(0xffffffffu, v, off);
        if (tid == 0) red[0] = v;
    }
    __syncthreads();
    float inv = rsqrtf(red[0] * (1.0f / D_MODEL) + 1e-5f);
    #pragma unroll
    for (int i = tid; i < D_MODEL; i += 256)
        orow[i] = xr[i] * inv * w[i];
}

// ---------------- TF32 GEMM (NT), 4 warps x 64x64, cp.async 3-stage ----------------
// Operands fed as raw fp32 bits (tf32 truncation). Epilogue modes:
//   R != 0:  C = acc + R   (residual; R may alias C)
//   G != 0:  C = silu(acc) * G   (fused SwiGLU)
__global__ __launch_bounds__(128, 2) void mma_tf32_nt_kernel(
    const float* __restrict__ A, const float* __restrict__ B,
    const float* R, const float* __restrict__ G,
    float* C, int M, int N, int K) {
    __shared__ float As[3][128 * 20];
    __shared__ float Bs[3][128 * 20];

    int tid  = threadIdx.x;
    int wid  = tid >> 5;
    int lane = tid & 31;
    int grp  = lane >> 2;
    int qid  = lane & 3;

    int wm = (wid & 1) * 64;
    int wn = (wid >> 1) * 64;

    int bx = blockIdx.x;
    int by = blockIdx.y;

    int rs  = tid >> 2;          // 0..31
    int kqs = (tid & 3) * 4;

    const float* Abase = A + (size_t)(by * 128 + rs) * K + kqs;
    const float* Bbase = B + (size_t)(bx * 128 + rs) * K + kqs;
    uint32_t sa[4], sb[4];
    #pragma unroll
    for (int i = 0; i < 4; i++) {
        sa[i] = smem_u32(&As[0][(rs + 32 * i) * 20 + kqs]);
        sb[i] = smem_u32(&Bs[0][(rs + 32 * i) * 20 + kqs]);
    }
    const uint32_t bufB = 128 * 20 * 4;

    float c[4][8][4];
    #pragma unroll
    for (int mt = 0; mt < 4; mt++)
        #pragma unroll
        for (int nt = 0; nt < 8; nt++)
            #pragma unroll
            for (int i = 0; i < 4; i++) c[mt][nt][i] = 0.f;

    int T = K / 16;

    // prefetch tiles 0 and 1
    #pragma unroll
    for (int p = 0; p < 2; p++) {
        uint32_t off = p * bufB;
        int k0 = p * 16;
        #pragma unroll
        for (int i = 0; i < 4; i++) {
            CP_ASYNC16(sa[i] + off, Abase + (size_t)(32 * i) * K + k0);
            CP_ASYNC16(sb[i] + off, Bbase + (size_t)(32 * i) * K + k0);
        }
        CP_COMMIT();
    }

    int stage = 0;
    for (int t = 0; t < T; t++) {
        if (t + 2 < T) {
            int k0 = (t + 2) * 16;
            uint32_t off = ((stage + 2) % 3) * bufB;
            #pragma unroll
            for (int i = 0; i < 4; i++) {
                CP_ASYNC16(sa[i] + off, Abase + (size_t)(32 * i) * K + k0);
                CP_ASYNC16(sb[i] + off, Bbase + (size_t)(32 * i) * K + k0);
            }
            CP_COMMIT();
            CP_WAIT(2);
        } else {
            CP_WAIT(0);
        }
        __syncthreads();

        const float* Asb = As[stage];
        const float* Bsb = Bs[stage];

        #pragma unroll
        for (int kk = 0; kk < 16; kk += 8) {
            uint32_t af[4][4], bf[8][2];
            #pragma unroll
            for (int mt = 0; mt < 4; mt++) {
                int r0 = wm + mt * 16 + grp;
                af[mt][0] = __float_as_uint(Asb[r0 * 20 + kk + qid]);
                af[mt][1] = __float_as_uint(Asb[(r0 + 8) * 20 + kk + qid]);
                af[mt][2] = __float_as_uint(Asb[r0 * 20 + kk + qid + 4]);
                af[mt][3] = __float_as_uint(Asb[(r0 + 8) * 20 + kk + qid + 4]);
            }
            #pragma unroll
            for (int nt = 0; nt < 8; nt++) {
                int n0 = wn + nt * 8 + grp;
                bf[nt][0] = __float_as_uint(Bsb[n0 * 20 + kk + qid]);
                bf[nt][1] = __float_as_uint(Bsb[n0 * 20 + kk + qid + 4]);
            }
            #pragma unroll
            for (int mt = 0; mt < 4; mt++)
                #pragma unroll
                for (int nt = 0; nt < 8; nt++)
                    MMA_TF32(c[mt][nt][0], c[mt][nt][1], c[mt][nt][2], c[mt][nt][3],
                             af[mt][0], af[mt][1], af[mt][2], af[mt][3],
                             bf[nt][0], bf[nt][1]);
        }
        __syncthreads();
        stage = (stage + 1) % 3;
    }

    #pragma unroll
    for (int mt = 0; mt < 4; mt++) {
        int row = by * 128 + wm + mt * 16 + grp;
        #pragma unroll
        for (int nt = 0; nt < 8; nt++) {
            int col = bx * 128 + wn + nt * 8 + qid * 2;
            size_t i0 = (size_t)row * N + col;
            size_t i1 = (size_t)(row + 8) * N + col;
            float v00 = c[mt][nt][0], v01 = c[mt][nt][1];
            float v10 = c[mt][nt][2], v11 = c[mt][nt][3];
            if (R) {
                v00 += R[i0]; v01 += R[i0 + 1];
                v10 += R[i1]; v11 += R[i1 + 1];
            }
            if (G) {
                v00 = v00 / (1.f + __expf(-v00)) * G[i0];
                v01 = v01 / (1.f + __expf(-v01)) * G[i0 + 1];
                v10 = v10 / (1.f + __expf(-v10)) * G[i1];
                v11 = v11 / (1.f + __expf(-v11)) * G[i1 + 1];
            }
            *(float2*)(C + i0) = make_float2(v00, v01);
            *(float2*)(C + i1) = make_float2(v10, v11);
        }
    }
}

// ---------------- RoPE (fp64 angles, out-of-place; validated) ----------------
__global__ void rope_dbl_kernel(const float* __restrict__ qin,
                                const float* __restrict__ kin,
                                float* __restrict__ qout,
                                float* __restrict__ kout,
                                const int* __restrict__ pos) {
    int bs = blockIdx.x;
    int h  = threadIdx.x >> 5;
    int i  = threadIdx.x & 31;
    int p  = pos[bs];

    double freq = exp(-((double)(2 * i) / 64.0) * log(10000.0));
    double ang = (double)p * freq;
    double cd, sd;
    sincos(ang, &sd, &cd);
    float c = (float)cd, s = (float)sd;

    size_t base = (size_t)bs * D_MODEL + h * DK + 2 * i;
    float qe = qin[base], qo = qin[base + 1];
    qout[base]     = qe * c - qo * s;
    qout[base + 1] = qe * s + qo * c;
    float ke = kin[base], ko = kin[base + 1];
    kout[base]     = ke * c - ko * s;
    kout[base + 1] = ke * s + ko * c;
}

// ---------------- Tensor-core causal flash attention (tf32 mma, raw-bit operands) ----------------
__global__ __launch_bounds__(256) void attn_mma_kernel(
    const float* __restrict__ Q, const float* __restrict__ K,
    const float* __restrict__ V, float* __restrict__ O) {
    __shared__ float Ks[64][68];
    __shared__ float Vs[64][68];

    int tid  = threadIdx.x;
    int wid  = tid >> 5;
    int lane = tid & 31;
    int grp  = lane >> 2;
    int qid  = lane & 3;

    int q0 = blockIdx.x * 128;
    int h  = blockIdx.y;
    int b  = blockIdx.z;

    int r0 = q0 + wid * 16 + grp;
    int r1 = r0 + 8;
    size_t headoff = (size_t)b * SEQ * D_MODEL + h * DK;

    uint32_t qa[8][4];
    {
        const float* q0p = Q + headoff + (size_t)r0 * D_MODEL;
        const float* q1p = Q + headoff + (size_t)r1 * D_MODEL;
        #pragma unroll
        for (int ks = 0; ks < 8; ks++) {
            qa[ks][0] = __float_as_uint(q0p[8 * ks + qid]);
            qa[ks][1] = __float_as_uint(q1p[8 * ks + qid]);
            qa[ks][2] = __float_as_uint(q0p[8 * ks + qid + 4]);
            qa[ks][3] = __float_as_uint(q1p[8 * ks + qid + 4]);
        }
    }

    float oc[8][4];
    #pragma unroll
    for (int nn = 0; nn < 8; nn++)
        #pragma unroll
        for (int i = 0; i < 4; i++) oc[nn][i] = 0.f;
    float m0 = -INFINITY, m1 = -INFINITY, l0 = 0.f, l1 = 0.f;
    const float scale = 0.125f;

    for (int kv = 0; kv < q0 + 128; kv += 64) {
        __syncthreads();
        for (int idx = tid; idx < 64 * 16; idx += 256) {
            int r = idx >> 4, c = (idx & 15) * 4;
            *(float4*)&Ks[r][c] =
                *(const float4*)(K + headoff + (size_t)(kv + r) * D_MODEL + c);
            *(float4*)&Vs[r][c] =
                *(const float4*)(V + headoff + (size_t)(kv + r) * D_MODEL + c);
        }
        __syncthreads();

        float sc[8][4];
        #pragma unroll
        for (int nn = 0; nn < 8; nn++) {
            sc[nn][0] = sc[nn][1] = sc[nn][2] = sc[nn][3] = 0.f;
            #pragma unroll
            for (int ks = 0; ks < 8; ks++) {
                uint32_t b0 = __float_as_uint(Ks[8 * nn + grp][8 * ks + qid]);
                uint32_t b1 = __float_as_uint(Ks[8 * nn + grp][8 * ks + qid + 4]);
                MMA_TF32(sc[nn][0], sc[nn][1], sc[nn][2], sc[nn][3],
                         qa[ks][0], qa[ks][1], qa[ks][2], qa[ks][3], b0, b1);
            }
        }

        #pragma unroll
        for (int nn = 0; nn < 8; nn++) {
            int col = kv + 8 * nn + 2 * qid;
            sc[nn][0] = (col     <= r0) ? sc[nn][0] * scale : -INFINITY;
            sc[nn][1] = (col + 1 <= r0) ? sc[nn][1] * scale : -INFINITY;
            sc[nn][2] = (col     <= r1) ? sc[nn][2] * scale : -INFINITY;
            sc[nn][3] = (col + 1 <= r1) ? sc[nn][3] * scale : -INFINITY;
        }

        float tm0 = -INFINITY, tm1 = -INFINITY;
        #pragma unroll
        for (int nn = 0; nn < 8; nn++) {
            tm0 = fmaxf(tm0, fmaxf(sc[nn][0], sc[nn][1]));
            tm1 = fmaxf(tm1, fmaxf(sc[nn][2], sc[nn][3]));
        }
        tm0 = fmaxf(tm0, __shfl_xor_sync(0xffffffffu, tm0, 1));
        tm0 = fmaxf(tm0, __shfl_xor_sync(0xffffffffu, tm0, 2));
        tm1 = fmaxf(tm1, __shfl_xor_sync(0xffffffffu, tm1, 1));
        tm1 = fmaxf(tm1, __shfl_xor_sync(0xffffffffu, tm1, 2));

        float nm0 = fmaxf(m0, tm0), nm1 = fmaxf(m1, tm1);
        float corr0 = __expf(m0 - nm0), corr1 = __expf(m1 - nm1);
        m0 = nm0; m1 = nm1;

        float sum0 = 0.f, sum1 = 0.f;
        #pragma unroll
        for (int nn = 0; nn < 8; nn++) {
            sc[nn][0] = __expf(sc[nn][0] - nm0);
            sc[nn][1] = __expf(sc[nn][1] - nm0);
            sc[nn][2] = __expf(sc[nn][2] - nm1);
            sc[nn][3] = __expf(sc[nn][3] - nm1);
            sum0 += sc[nn][0] + sc[nn][1];
            sum1 += sc[nn][2] + sc[nn][3];
        }
        sum0 += __shfl_xor_sync(0xffffffffu, sum0, 1);
        sum0 += __shfl_xor_sync(0xffffffffu, sum0, 2);
        sum1 += __shfl_xor_sync(0xffffffffu, sum1, 1);
        sum1 += __shfl_xor_sync(0xffffffffu, sum1, 2);
        l0 = l0 * corr0 + sum0;
        l1 = l1 * corr1 + sum1;

        #pragma unroll
        for (int nn = 0; nn < 8; nn++) {
            oc[nn][0] *= corr0; oc[nn][1] *= corr0;
            oc[nn][2] *= corr1; oc[nn][3] *= corr1;
        }

        int srcA = (lane & ~3) | (qid >> 1);
        int srcB = srcA + 2;
        #pragma unroll
        for (int ks = 0; ks < 8; ks++) {
            float t0 = __shfl_sync(0xffffffffu, sc[ks][0], srcA);
            float t1 = __shfl_sync(0xffffffffu, sc[ks][1], srcA);
            float u0 = __shfl_sync(0xffffffffu, sc[ks][2], srcA);
            float u1 = __shfl_sync(0xffffffffu, sc[ks][3], srcA);
            float w0 = __shfl_sync(0xffffffffu, sc[ks][0], srcB);
            float w1 = __shfl_sync(0xffffffffu, sc[ks][1], srcB);
            float x0 = __shfl_sync(0xffffffffu, sc[ks][2], srcB);
            float x1 = __shfl_sync(0xffffffffu, sc[ks][3], srcB);
            uint32_t a0 = f2tf32((qid & 1) ? t1 : t0);
            uint32_t a1 = f2tf32((qid & 1) ? u1 : u0);
            uint32_t a2 = f2tf32((qid & 1) ? w1 : w0);
            uint32_t a3 = f2tf32((qid & 1) ? x1 : x0);
            #pragma unroll
            for (int nn = 0; nn < 8; nn++) {
                uint32_t b0 = __float_as_uint(Vs[8 * ks + qid][8 * nn + grp]);
                uint32_t b1 = __float_as_uint(Vs[8 * ks + qid + 4][8 * nn + grp]);
                MMA_TF32(oc[nn][0], oc[nn][1], oc[nn][2], oc[nn][3],
                         a0, a1, a2, a3, b0, b1);
            }
        }
    }

    float inv0 = 1.f / l0, inv1 = 1.f / l1;
    float* o0 = O + headoff + (size_t)r0 * D_MODEL;
    float* o1 = O + headoff + (size_t)r1 * D_MODEL;
    #pragma unroll
    for (int nn = 0; nn < 8; nn++) {
        int col = 8 * nn + 2 * qid;
        *(float2*)(o0 + col) = make_float2(oc[nn][0] * inv0, oc[nn][1] * inv0);
        *(float2*)(o1 + col) = make_float2(oc[nn][2] * inv1, oc[nn][3] * inv1);
    }
}

// ---------------- launch ----------------
extern "C" void kernel_launch(void* const* d_in, const int* in_sizes, int n_in,
                              void* d_out, int out_size) {
    const float* x    = (const float*)d_in[0];
    const int*   pos  = (const int*)  d_in[1];
    const float* n1w  = (const float*)d_in[2];
    const float* n2w  = (const float*)d_in[3];
    const float* wq   = (const float*)d_in[4];
    const float* wk   = (const float*)d_in[5];
    const float* wv   = (const float*)d_in[6];
    const float* wo   = (const float*)d_in[7];
    const float* w1   = (const float*)d_in[8];
    const float* w2   = (const float*)d_in[9];
    const float* w3   = (const float*)d_in[10];
    float* out = (float*)d_out;

    float *xn, *q, *k, *v, *q2, *k2, *attn, *a, *g;
    cudaGetSymbolAddress((void**)&xn,   g_xn);
    cudaGetSymbolAddress((void**)&q,    g_q);
    cudaGetSymbolAddress((void**)&k,    g_k);
    cudaGetSymbolAddress((void**)&v,    g_v);
    cudaGetSymbolAddress((void**)&q2,   g_q2);
    cudaGetSymbolAddress((void**)&k2,   g_k2);
    cudaGetSymbolAddress((void**)&attn, g_attn);
    cudaGetSymbolAddress((void**)&a,    g_a);
    cudaGetSymbolAddress((void**)&g,    g_g);

    // 1) xn = rmsnorm(x, norm1_w)
    rmsnorm_kernel<<<MROWS, 256>>>(x, n1w, xn);

    // 2) q/k/v projections
    dim3 gD(D_MODEL / 128, MROWS / 128);
    mma_tf32_nt_kernel<<<gD, 128>>>(xn, wq, nullptr, nullptr, q, MROWS, D_MODEL, D_MODEL);
    mma_tf32_nt_kernel<<<gD, 128>>>(xn, wk, nullptr, nullptr, k, MROWS, D_MODEL, D_MODEL);
    mma_tf32_nt_kernel<<<gD, 128>>>(xn, wv, nullptr, nullptr, v, MROWS, D_MODEL, D_MODEL);

    // 3) RoPE (out-of-place)
    rope_dbl_kernel<<<MROWS, 512>>>(q, k, q2, k2, pos);

    // 4) tensor-core causal flash attention
    attn_mma_kernel<<<dim3(SEQ / 128, HEADS, BATCH), 256>>>(q2, k2, v, attn);

    // 5) out = x + attn @ wo^T
    mma_tf32_nt_kernel<<<gD, 128>>>(attn, wo, x, nullptr, out, MROWS, D_MODEL, D_MODEL);

    // 6) xn = rmsnorm(out, norm2_w)
    rmsnorm_kernel<<<MROWS, 256>>>(out, n2w, xn);

    // 7) g = xn @ w3^T ; a = silu(xn @ w1^T) * g   (fused epilogue)
    dim3 gF(DFF / 128, MROWS / 128);
    mma_tf32_nt_kernel<<<gF, 128>>>(xn, w3, nullptr, nullptr, g, MROWS, DFF, D_MODEL);
    mma_tf32_nt_kernel<<<gF, 128>>>(xn, w1, nullptr, g, a, MROWS, DFF, D_MODEL);

    // 8) out = out + a @ w2^T   (R == C aliasing legal: no restrict)
    mma_tf32_nt_kernel<<<gD, 128>>>(a, w2, out, nullptr, out, MROWS, D_MODEL, DFF);
}

// round 16
// speedup vs baseline: 5.2012x; 1.0991x over previous
#include <cuda_runtime.h>
#include <math.h>
#include <stdint.h>

#define D_MODEL 1024
#define SEQ     2048
#define BATCH   2
#define HEADS   16
#define DK      64
#define DFF     4096
#define MROWS   (BATCH * SEQ)   // 4096

// ---------------- scratch (static device allocations) ----------------
__device__ float g_xn  [MROWS * D_MODEL];
__device__ float g_q   [MROWS * D_MODEL];
__device__ float g_k   [MROWS * D_MODEL];
__device__ float g_v   [MROWS * D_MODEL];
__device__ float g_q2  [MROWS * D_MODEL];
__device__ float g_k2  [MROWS * D_MODEL];
__device__ float g_attn[MROWS * D_MODEL];
__device__ float g_a   [(size_t)MROWS * DFF];
__device__ float g_g   [(size_t)MROWS * DFF];

__device__ __forceinline__ uint32_t f2tf32(float f) {
    uint32_t u;
    asm("cvt.rna.tf32.f32 %0, %1;" : "=r"(u) : "f"(f));
    return u;
}
__device__ __forceinline__ float rtf32(float f) {
    return __uint_as_float(f2tf32(f));
}
__device__ __forceinline__ uint32_t smem_u32(const void* p) {
    return (uint32_t)__cvta_generic_to_shared(p);
}

#define CP_ASYNC16(dst, src) \
    asm volatile("cp.async.ca.shared.global [%0], [%1], 16;\n" :: "r"(dst), "l"(src))
#define CP_COMMIT() asm volatile("cp.async.commit_group;\n" ::: "memory")
#define CP_WAIT(n)  asm volatile("cp.async.wait_group %0;\n" :: "n"(n) : "memory")

#define MMA_TF32(c0,c1,c2,c3,a0,a1,a2,a3,b0,b1)                         \
    asm volatile(                                                        \
        "mma.sync.aligned.m16n8k8.row.col.f32.tf32.tf32.f32 "           \
        "{%0,%1,%2,%3}, {%4,%5,%6,%7}, {%8,%9}, {%0,%1,%2,%3};"         \
        : "+f"(c0), "+f"(c1), "+f"(c2), "+f"(c3)                         \
        : "r"(a0), "r"(a1), "r"(a2), "r"(a3), "r"(b0), "r"(b1))

// epilogue mode bits
#define EPI_RES   1   // += R (may alias C)
#define EPI_SILU  2   // C = silu(acc) * G
#define EPI_ROUND 4   // round C to tf32

// ---------------- RMSNorm (tf32-rounded output) ----------------
__global__ void rmsnorm_kernel(const float* __restrict__ x,
                               const float* __restrict__ w,
                               float* __restrict__ o) {
    int row = blockIdx.x;
    const float* xr = x + (size_t)row * D_MODEL;
    float* orow = o + (size_t)row * D_MODEL;
    int tid = threadIdx.x;

    float s = 0.f;
    #pragma unroll
    for (int i = tid; i < D_MODEL; i += 256) {
        float v = xr[i];
        s += v * v;
    }
    #pragma unroll
    for (int off = 16; off > 0; off >>= 1)
        s += __shfl_xor_sync(0xffffffffu, s, off);
    __shared__ float red[8];
    if ((tid & 31) == 0) red[tid >> 5] = s;
    __syncthreads();
    if (tid < 32) {
        float v = (tid < 8) ? red[tid] : 0.f;
        #pragma unroll
        for (int off = 4; off > 0; off >>= 1)
            v += __shfl_xor_sync(0xffffffffu, v, off);
        if (tid == 0) red[0] = v;
    }
    __syncthreads();
    float inv = rsqrtf(red[0] * (1.0f / D_MODEL) + 1e-5f);
    #pragma unroll
    for (int i = tid; i < D_MODEL; i += 256)
        orow[i] = rtf32(xr[i] * inv * w[i]);
}

// ---------------- TF32 GEMM (NT), 4 warps x 64x64, BK=32, cp.async 2-stage ----------------
// A (activations) pre-rounded -> raw bits. B (weights) cvt.rna in-loop.
// R/C not __restrict__ (final FFN GEMM passes R==C==d_out).
__global__ __launch_bounds__(128, 2) void mma_tf32_nt_kernel(
    const float* __restrict__ A, const float* __restrict__ B,
    const float* R, const float* __restrict__ G,
    float* C, int M, int N, int K, int mode) {
    __shared__ float As[2][128 * 36];
    __shared__ float Bs[2][128 * 36];

    int tid  = threadIdx.x;
    int wid  = tid >> 5;
    int lane = tid & 31;
    int grp  = lane >> 2;
    int qid  = lane & 3;

    int wm = (wid & 1) * 64;
    int wn = (wid >> 1) * 64;

    int bx = blockIdx.x;
    int by = blockIdx.y;

    // staging: 8 float4 per thread per matrix; f = tid + i*128, r = f>>3, kq = (f&7)*4
    const uint32_t bufB = 128 * 36 * 4;
    uint32_t sa[8], sb[8];
    const float *Ag[8], *Bg[8];
    #pragma unroll
    for (int i = 0; i < 8; i++) {
        int f = tid + i * 128;
        int r = f >> 3;
        int kq = (f & 7) * 4;
        sa[i] = smem_u32(&As[0][r * 36 + kq]);
        sb[i] = smem_u32(&Bs[0][r * 36 + kq]);
        Ag[i] = A + (size_t)(by * 128 + r) * K + kq;
        Bg[i] = B + (size_t)(bx * 128 + r) * K + kq;
    }

    float c[4][8][4];
    #pragma unroll
    for (int mt = 0; mt < 4; mt++)
        #pragma unroll
        for (int nt = 0; nt < 8; nt++)
            #pragma unroll
            for (int i = 0; i < 4; i++) c[mt][nt][i] = 0.f;

    int T = K / 32;

    // prefetch tile 0
    #pragma unroll
    for (int i = 0; i < 8; i++) {
        CP_ASYNC16(sa[i], Ag[i]);
        CP_ASYNC16(sb[i], Bg[i]);
    }
    CP_COMMIT();

    for (int t = 0; t < T; t++) {
        if (t + 1 < T) {
            int k0 = (t + 1) * 32;
            uint32_t off = ((t + 1) & 1) * bufB;
            #pragma unroll
            for (int i = 0; i < 8; i++) {
                CP_ASYNC16(sa[i] + off, Ag[i] + k0);
                CP_ASYNC16(sb[i] + off, Bg[i] + k0);
            }
            CP_COMMIT();
            CP_WAIT(1);
        } else {
            CP_WAIT(0);
        }
        __syncthreads();

        const float* Asb = As[t & 1];
        const float* Bsb = Bs[t & 1];

        #pragma unroll
        for (int kk = 0; kk < 32; kk += 8) {
            uint32_t af[4][4], bf[8][2];
            #pragma unroll
            for (int mt = 0; mt < 4; mt++) {
                int r0 = wm + mt * 16 + grp;
                af[mt][0] = __float_as_uint(Asb[r0 * 36 + kk + qid]);
                af[mt][1] = __float_as_uint(Asb[(r0 + 8) * 36 + kk + qid]);
                af[mt][2] = __float_as_uint(Asb[r0 * 36 + kk + qid + 4]);
                af[mt][3] = __float_as_uint(Asb[(r0 + 8) * 36 + kk + qid + 4]);
            }
            #pragma unroll
            for (int nt = 0; nt < 8; nt++) {
                int n0 = wn + nt * 8 + grp;
                bf[nt][0] = f2tf32(Bsb[n0 * 36 + kk + qid]);
                bf[nt][1] = f2tf32(Bsb[n0 * 36 + kk + qid + 4]);
            }
            #pragma unroll
            for (int mt = 0; mt < 4; mt++)
                #pragma unroll
                for (int nt = 0; nt < 8; nt++)
                    MMA_TF32(c[mt][nt][0], c[mt][nt][1], c[mt][nt][2], c[mt][nt][3],
                             af[mt][0], af[mt][1], af[mt][2], af[mt][3],
                             bf[nt][0], bf[nt][1]);
        }
        __syncthreads();
    }

    #pragma unroll
    for (int mt = 0; mt < 4; mt++) {
        int row = by * 128 + wm + mt * 16 + grp;
        #pragma unroll
        for (int nt = 0; nt < 8; nt++) {
            int col = bx * 128 + wn + nt * 8 + qid * 2;
            size_t i0 = (size_t)row * N + col;
            size_t i1 = (size_t)(row + 8) * N + col;
            float v00 = c[mt][nt][0], v01 = c[mt][nt][1];
            float v10 = c[mt][nt][2], v11 = c[mt][nt][3];
            if (mode & EPI_RES) {
                v00 += R[i0]; v01 += R[i0 + 1];
                v10 += R[i1]; v11 += R[i1 + 1];
            }
            if (mode & EPI_SILU) {
                v00 = v00 / (1.f + __expf(-v00)) * G[i0];
                v01 = v01 / (1.f + __expf(-v01)) * G[i0 + 1];
                v10 = v10 / (1.f + __expf(-v10)) * G[i1];
                v11 = v11 / (1.f + __expf(-v11)) * G[i1 + 1];
            }
            if (mode & EPI_ROUND) {
                v00 = rtf32(v00); v01 = rtf32(v01);
                v10 = rtf32(v10); v11 = rtf32(v11);
            }
            *(float2*)(C + i0) = make_float2(v00, v01);
            *(float2*)(C + i1) = make_float2(v10, v11);
        }
    }
}

// ---------------- RoPE (fp64 angles, out-of-place, tf32-rounded) ----------------
__global__ void rope_dbl_kernel(const float* __restrict__ qin,
                                const float* __restrict__ kin,
                                float* __restrict__ qout,
                                float* __restrict__ kout,
                                const int* __restrict__ pos) {
    int bs = blockIdx.x;
    int h  = threadIdx.x >> 5;
    int i  = threadIdx.x & 31;
    int p  = pos[bs];

    double freq = exp(-((double)(2 * i) / 64.0) * log(10000.0));
    double ang = (double)p * freq;
    double cd, sd;
    sincos(ang, &sd, &cd);
    float c = (float)cd, s = (float)sd;

    size_t base = (size_t)bs * D_MODEL + h * DK + 2 * i;
    float qe = qin[base], qo = qin[base + 1];
    qout[base]     = rtf32(qe * c - qo * s);
    qout[base + 1] = rtf32(qe * s + qo * c);
    float ke = kin[base], ko = kin[base + 1];
    kout[base]     = rtf32(ke * c - ko * s);
    kout[base + 1] = rtf32(ke * s + ko * c);
}

// ---------------- Tensor-core causal flash attention (tf32 mma) ----------------
// Q/K/V pre-rounded -> raw-bit operands. O tf32-rounded (feeds wo GEMM).
__global__ __launch_bounds__(256) void attn_mma_kernel(
    const float* __restrict__ Q, const float* __restrict__ K,
    const float* __restrict__ V, float* __restrict__ O) {
    __shared__ float Ks[64][68];
    __shared__ float Vs[64][68];

    int tid  = threadIdx.x;
    int wid  = tid >> 5;
    int lane = tid & 31;
    int grp  = lane >> 2;
    int qid  = lane & 3;

    int q0 = blockIdx.x * 128;
    int h  = blockIdx.y;
    int b  = blockIdx.z;

    int r0 = q0 + wid * 16 + grp;
    int r1 = r0 + 8;
    size_t headoff = (size_t)b * SEQ * D_MODEL + h * DK;

    uint32_t qa[8][4];
    {
        const float* q0p = Q + headoff + (size_t)r0 * D_MODEL;
        const float* q1p = Q + headoff + (size_t)r1 * D_MODEL;
        #pragma unroll
        for (int ks = 0; ks < 8; ks++) {
            qa[ks][0] = __float_as_uint(q0p[8 * ks + qid]);
            qa[ks][1] = __float_as_uint(q1p[8 * ks + qid]);
            qa[ks][2] = __float_as_uint(q0p[8 * ks + qid + 4]);
            qa[ks][3] = __float_as_uint(q1p[8 * ks + qid + 4]);
        }
    }

    float oc[8][4];
    #pragma unroll
    for (int nn = 0; nn < 8; nn++)
        #pragma unroll
        for (int i = 0; i < 4; i++) oc[nn][i] = 0.f;
    float m0 = -INFINITY, m1 = -INFINITY, l0 = 0.f, l1 = 0.f;
    const float scale = 0.125f;

    for (int kv = 0; kv < q0 + 128; kv += 64) {
        __syncthreads();
        for (int idx = tid; idx < 64 * 16; idx += 256) {
            int r = idx >> 4, c = (idx & 15) * 4;
            *(float4*)&Ks[r][c] =
                *(const float4*)(K + headoff + (size_t)(kv + r) * D_MODEL + c);
            *(float4*)&Vs[r][c] =
                *(const float4*)(V + headoff + (size_t)(kv + r) * D_MODEL + c);
        }
        __syncthreads();

        float sc[8][4];
        #pragma unroll
        for (int nn = 0; nn < 8; nn++) {
            sc[nn][0] = sc[nn][1] = sc[nn][2] = sc[nn][3] = 0.f;
            #pragma unroll
            for (int ks = 0; ks < 8; ks++) {
                uint32_t b0 = __float_as_uint(Ks[8 * nn + grp][8 * ks + qid]);
                uint32_t b1 = __float_as_uint(Ks[8 * nn + grp][8 * ks + qid + 4]);
                MMA_TF32(sc[nn][0], sc[nn][1], sc[nn][2], sc[nn][3],
                         qa[ks][0], qa[ks][1], qa[ks][2], qa[ks][3], b0, b1);
            }
        }

        #pragma unroll
        for (int nn = 0; nn < 8; nn++) {
            int col = kv + 8 * nn + 2 * qid;
            sc[nn][0] = (col     <= r0) ? sc[nn][0] * scale : -INFINITY;
            sc[nn][1] = (col + 1 <= r0) ? sc[nn][1] * scale : -INFINITY;
            sc[nn][2] = (col     <= r1) ? sc[nn][2] * scale : -INFINITY;
            sc[nn][3] = (col + 1 <= r1) ? sc[nn][3] * scale : -INFINITY;
        }

        float tm0 = -INFINITY, tm1 = -INFINITY;
        #pragma unroll
        for (int nn = 0; nn < 8; nn++) {
            tm0 = fmaxf(tm0, fmaxf(sc[nn][0], sc[nn][1]));
            tm1 = fmaxf(tm1, fmaxf(sc[nn][2], sc[nn][3]));
        }
        tm0 = fmaxf(tm0, __shfl_xor_sync(0xffffffffu, tm0, 1));
        tm0 = fmaxf(tm0, __shfl_xor_sync(0xffffffffu, tm0, 2));
        tm1 = fmaxf(tm1, __shfl_xor_sync(0xffffffffu, tm1, 1));
        tm1 = fmaxf(tm1, __shfl_xor_sync(0xffffffffu, tm1, 2));

        float nm0 = fmaxf(m0, tm0), nm1 = fmaxf(m1, tm1);
        float corr0 = __expf(m0 - nm0), corr1 = __expf(m1 - nm1);
        m0 = nm0; m1 = nm1;

        float sum0 = 0.f, sum1 = 0.f;
        #pragma unroll
        for (int nn = 0; nn < 8; nn++) {
            sc[nn][0] = __expf(sc[nn][0] - nm0);
            sc[nn][1] = __expf(sc[nn][1] - nm0);
            sc[nn][2] = __expf(sc[nn][2] - nm1);
            sc[nn][3] = __expf(sc[nn][3] - nm1);
            sum0 += sc[nn][0] + sc[nn][1];
            sum1 += sc[nn][2] + sc[nn][3];
        }
        sum0 += __shfl_xor_sync(0xffffffffu, sum0, 1);
        sum0 += __shfl_xor_sync(0xffffffffu, sum0, 2);
        sum1 += __shfl_xor_sync(0xffffffffu, sum1, 1);
        sum1 += __shfl_xor_sync(0xffffffffu, sum1, 2);
        l0 = l0 * corr0 + sum0;
        l1 = l1 * corr1 + sum1;

        #pragma unroll
        for (int nn = 0; nn < 8; nn++) {
            oc[nn][0] *= corr0; oc[nn][1] *= corr0;
            oc[nn][2] *= corr1; oc[nn][3] *= corr1;
        }

        int srcA = (lane & ~3) | (qid >> 1);
        int srcB = srcA + 2;
        #pragma unroll
        for (int ks = 0; ks < 8; ks++) {
            float t0 = __shfl_sync(0xffffffffu, sc[ks][0], srcA);
            float t1 = __shfl_sync(0xffffffffu, sc[ks][1], srcA);
            float u0 = __shfl_sync(0xffffffffu, sc[ks][2], srcA);
            float u1 = __shfl_sync(0xffffffffu, sc[ks][3], srcA);
            float w0 = __shfl_sync(0xffffffffu, sc[ks][0], srcB);
            float w1 = __shfl_sync(0xffffffffu, sc[ks][1], srcB);
            float x0 = __shfl_sync(0xffffffffu, sc[ks][2], srcB);
            float x1 = __shfl_sync(0xffffffffu, sc[ks][3], srcB);
            uint32_t a0 = f2tf32((qid & 1) ? t1 : t0);
            uint32_t a1 = f2tf32((qid & 1) ? u1 : u0);
            uint32_t a2 = f2tf32((qid & 1) ? w1 : w0);
            uint32_t a3 = f2tf32((qid & 1) ? x1 : x0);
            #pragma unroll
            for (int nn = 0; nn < 8; nn++) {
                uint32_t b0 = __float_as_uint(Vs[8 * ks + qid][8 * nn + grp]);
                uint32_t b1 = __float_as_uint(Vs[8 * ks + qid + 4][8 * nn + grp]);
                MMA_TF32(oc[nn][0], oc[nn][1], oc[nn][2], oc[nn][3],
                         a0, a1, a2, a3, b0, b1);
            }
        }
    }

    float inv0 = 1.f / l0, inv1 = 1.f / l1;
    float* o0 = O + headoff + (size_t)r0 * D_MODEL;
    float* o1 = O + headoff + (size_t)r1 * D_MODEL;
    #pragma unroll
    for (int nn = 0; nn < 8; nn++) {
        int col = 8 * nn + 2 * qid;
        *(float2*)(o0 + col) = make_float2(rtf32(oc[nn][0] * inv0), rtf32(oc[nn][1] * inv0));
        *(float2*)(o1 + col) = make_float2(rtf32(oc[nn][2] * inv1), rtf32(oc[nn][3] * inv1));
    }
}

// ---------------- launch ----------------
extern "C" void kernel_launch(void* const* d_in, const int* in_sizes, int n_in,
                              void* d_out, int out_size) {
    const float* x    = (const float*)d_in[0];
    const int*   pos  = (const int*)  d_in[1];
    const float* n1w  = (const float*)d_in[2];
    const float* n2w  = (const float*)d_in[3];
    const float* wq   = (const float*)d_in[4];
    const float* wk   = (const float*)d_in[5];
    const float* wv   = (const float*)d_in[6];
    const float* wo   = (const float*)d_in[7];
    const float* w1   = (const float*)d_in[8];
    const float* w2   = (const float*)d_in[9];
    const float* w3   = (const float*)d_in[10];
    float* out = (float*)d_out;

    float *xn, *q, *k, *v, *q2, *k2, *attn, *a, *g;
    cudaGetSymbolAddress((void**)&xn,   g_xn);
    cudaGetSymbolAddress((void**)&q,    g_q);
    cudaGetSymbolAddress((void**)&k,    g_k);
    cudaGetSymbolAddress((void**)&v,    g_v);
    cudaGetSymbolAddress((void**)&q2,   g_q2);
    cudaGetSymbolAddress((void**)&k2,   g_k2);
    cudaGetSymbolAddress((void**)&attn, g_attn);
    cudaGetSymbolAddress((void**)&a,    g_a);
    cudaGetSymbolAddress((void**)&g,    g_g);

    // 1) xn = rmsnorm(x, norm1_w)  [rounded]
    rmsnorm_kernel<<<MROWS, 256>>>(x, n1w, xn);

    // 2) q/k/v projections; v rounded (feeds attention directly)
    dim3 gD(D_MODEL / 128, MROWS / 128);
    mma_tf32_nt_kernel<<<gD, 128>>>(xn, wq, nullptr, nullptr, q, MROWS, D_MODEL, D_MODEL, 0);
    mma_tf32_nt_kernel<<<gD, 128>>>(xn, wk, nullptr, nullptr, k, MROWS, D_MODEL, D_MODEL, 0);
    mma_tf32_nt_kernel<<<gD, 128>>>(xn, wv, nullptr, nullptr, v, MROWS, D_MODEL, D_MODEL, EPI_ROUND);

    // 3) RoPE (rounded outputs)
    rope_dbl_kernel<<<MROWS, 512>>>(q, k, q2, k2, pos);

    // 4) tensor-core causal flash attention (rounded O)
    attn_mma_kernel<<<dim3(SEQ / 128, HEADS, BATCH), 256>>>(q2, k2, v, attn);

    // 5) out = x + attn @ wo^T  (fp32 residual, unrounded)
    mma_tf32_nt_kernel<<<gD, 128>>>(attn, wo, x, nullptr, out, MROWS, D_MODEL, D_MODEL, EPI_RES);

    // 6) xn = rmsnorm(out, norm2_w)  [rounded]
    rmsnorm_kernel<<<MROWS, 256>>>(out, n2w, xn);

    // 7) g = xn @ w3^T ; a = silu(xn @ w1^T) * g  [fused, rounded]
    dim3 gF(DFF / 128, MROWS / 128);
    mma_tf32_nt_kernel<<<gF, 128>>>(xn, w3, nullptr, nullptr, g, MROWS, DFF, D_MODEL, 0);
    mma_tf32_nt_kernel<<<gF, 128>>>(xn, w1, nullptr, g, a, MROWS, DFF, D_MODEL, EPI_SILU | EPI_ROUND);

    // 8) out = out + a @ w2^T   (R == C aliasing legal: no restrict)
    mma_tf32_nt_kernel<<<gD, 128>>>(a, w2, out, nullptr, out, MROWS, D_MODEL, DFF, EPI_RES);
}